// round 12
// baseline (speedup 1.0000x reference)
#include <cuda_runtime.h>
#include <cuda_fp16.h>
#include <cstdint>
#include <math.h>

// Problem constants
#define S_LEN 4096
#define D_DIM 1024
#define NH    16
#define HDIM  64
#define FF_D  4096
#define KT    64
#define QKV_N 3072

#define EPI_NONE      0
#define EPI_BIAS      1
#define EPI_BIAS_RES  2
#define EPI_BIAS_GELU 3

// ---------------- scratch (device globals: allocation-free rule) ----------------
__device__ __half g_y   [S_LEN * D_DIM];
__device__ __half g_qkv [S_LEN * QKV_N];             // [S][3072]: q | k | v
__device__ __half g_o   [S_LEN * D_DIM];
__device__ __half g_ffn [(long long)S_LEN * FF_D];
__device__ __half g_Wqkv[(long long)D_DIM * QKV_N];  // [1024][3072] K-major
__device__ __half g_WoH [D_DIM * D_DIM];             // [1024][1024] K-major
__device__ __half g_W1H [(long long)D_DIM * FF_D];   // [1024][4096] K-major
__device__ __half g_W2H [(long long)FF_D * D_DIM];   // [4096][1024] K-major
__device__ float  g_x1  [S_LEN * D_DIM];
__device__ float  g_bqkv[QKV_N];

// ---------------- helpers ----------------
__device__ __forceinline__ uint32_t smem_u32(const void* p) {
    uint32_t a;
    asm("{ .reg .u64 t; cvta.to.shared.u64 t, %1; cvt.u32.u64 %0, t; }" : "=r"(a) : "l"(p));
    return a;
}
__device__ __forceinline__ void cp_async16(uint32_t s, const void* g) {
    asm volatile("cp.async.cg.shared.global [%0], [%1], 16;" :: "r"(s), "l"(g));
}
__device__ __forceinline__ void cp_commit() {
    asm volatile("cp.async.commit_group;" ::: "memory");
}
__device__ __forceinline__ void cp_wait(int n) {
    if (n == 0)      asm volatile("cp.async.wait_group 0;" ::: "memory");
    else if (n == 1) asm volatile("cp.async.wait_group 1;" ::: "memory");
    else             asm volatile("cp.async.wait_group 2;" ::: "memory");
}
__device__ __forceinline__ void ldsm4(uint32_t* r, uint32_t a) {
    asm volatile("ldmatrix.sync.aligned.m8n8.x4.shared.b16 {%0,%1,%2,%3}, [%4];"
        : "=r"(r[0]), "=r"(r[1]), "=r"(r[2]), "=r"(r[3]) : "r"(a));
}
__device__ __forceinline__ void ldsm4t(uint32_t* r, uint32_t a) {
    asm volatile("ldmatrix.sync.aligned.m8n8.x4.trans.shared.b16 {%0,%1,%2,%3}, [%4];"
        : "=r"(r[0]), "=r"(r[1]), "=r"(r[2]), "=r"(r[3]) : "r"(a));
}
__device__ __forceinline__ void mma_f16(float* c, const uint32_t* a,
                                        uint32_t b0, uint32_t b1) {
    asm volatile(
        "mma.sync.aligned.m16n8k16.row.col.f32.f16.f16.f32 "
        "{%0,%1,%2,%3}, {%4,%5,%6,%7}, {%8,%9}, {%0,%1,%2,%3};"
        : "+f"(c[0]), "+f"(c[1]), "+f"(c[2]), "+f"(c[3])
        : "r"(a[0]), "r"(a[1]), "r"(a[2]), "r"(a[3]), "r"(b0), "r"(b1));
}
__device__ __forceinline__ uint32_t h2exp2_(uint32_t x) {
    uint32_t r;
    asm("ex2.approx.f16x2 %0, %1;" : "=r"(r) : "r"(x));
    return r;
}
__device__ __forceinline__ float gelu_exact(float v) {
    return 0.5f * v * (1.0f + erff(v * 0.70710678118654752f));
}

// ---------------- LayerNorm (fp32 in, fp16 out) ----------------
__global__ __launch_bounds__(256) void ln_kernel(const float* __restrict__ x,
                                                 const float* __restrict__ sc,
                                                 const float* __restrict__ bi,
                                                 __half* __restrict__ y)
{
    long long row = blockIdx.x;
    const float* xr = x + row * D_DIM;
    int c = threadIdx.x << 2;
    float4 xv = *(const float4*)(xr + c);
    float s  = xv.x + xv.y + xv.z + xv.w;
    float ss = xv.x*xv.x + xv.y*xv.y + xv.z*xv.z + xv.w*xv.w;
    #pragma unroll
    for (int off = 16; off; off >>= 1) {
        s  += __shfl_down_sync(0xffffffffu, s,  off);
        ss += __shfl_down_sync(0xffffffffu, ss, off);
    }
    __shared__ float sbuf[8], ssbuf[8];
    __shared__ float mu_s, rinv_s;
    int w = threadIdx.x >> 5, l = threadIdx.x & 31;
    if (l == 0) { sbuf[w] = s; ssbuf[w] = ss; }
    __syncthreads();
    if (threadIdx.x == 0) {
        float S = 0.f, SS = 0.f;
        #pragma unroll
        for (int i = 0; i < 8; i++) { S += sbuf[i]; SS += ssbuf[i]; }
        float mu  = S * (1.0f / D_DIM);
        float var = SS * (1.0f / D_DIM) - mu * mu;
        mu_s = mu;
        rinv_s = rsqrtf(var + 1e-6f);
    }
    __syncthreads();
    float mu = mu_s, rinv = rinv_s;
    float4 scv = *(const float4*)(sc + c);
    float4 bv  = *(const float4*)(bi + c);
    __half2 h0 = __floats2half2_rn((xv.x - mu) * rinv * scv.x + bv.x,
                                   (xv.y - mu) * rinv * scv.y + bv.y);
    __half2 h1 = __floats2half2_rn((xv.z - mu) * rinv * scv.z + bv.z,
                                   (xv.w - mu) * rinv * scv.w + bv.w);
    uint2 pk;
    pk.x = *(uint32_t*)&h0; pk.y = *(uint32_t*)&h1;
    *(uint2*)(y + row * D_DIM + c) = pk;
}

// ---------------- RoPE (half in place, row stride ld) ----------------
__global__ void rope_kernel(__half* __restrict__ buf, int ld, float scale)
{
    int c = threadIdx.x;                 // 0..31
    int s = blockIdx.x;
    int h = blockIdx.y;
    __half* p = buf + (long long)s * ld + h * HDIM;
    float freq = expf(-(float)c * (9.210340371976184f / 32.0f));
    float ang = (float)s * freq;
    float sn, cs;
    sincosf(ang, &sn, &cs);
    float x1 = __half2float(p[c]), x2 = __half2float(p[c + 32]);
    p[c]      = __float2half_rn((x1 * cs - x2 * sn) * scale);
    p[c + 32] = __float2half_rn((x2 * cs + x1 * sn) * scale);
}

// ---------------- concat 3 bias vectors ----------------
__global__ void concat3_kernel(const float* __restrict__ a, const float* __restrict__ b,
                               const float* __restrict__ c, float* __restrict__ out)
{
    int i = blockIdx.x * 256 + threadIdx.x;
    out[i] = (i < 1024) ? a[i] : ((i < 2048) ? b[i - 1024] : c[i - 2048]);
}

// ---------------- fp32 -> fp16 convert, layout-preserving with row remap ----------------
// out[k*ldout + off + n] = in[k*ncols + n];  ncols % 4 == 0
__global__ __launch_bounds__(256) void cvt_kernel(const float* __restrict__ in,
                                                  __half* __restrict__ out,
                                                  int ncols, int ldout, int off)
{
    long long i4 = (long long)blockIdx.x * 256 + threadIdx.x;   // float4 index
    int nq = ncols >> 2;
    long long k = i4 / nq;
    int n = (int)(i4 % nq) << 2;
    float4 v = *(const float4*)(in + k * ncols + n);
    __half2 h0 = __floats2half2_rn(v.x, v.y);
    __half2 h1 = __floats2half2_rn(v.z, v.w);
    uint2 pk;
    pk.x = *(uint32_t*)&h0; pk.y = *(uint32_t*)&h1;
    *(uint2*)(out + k * ldout + off + n) = pk;
}

// ---------------- fused flash attention (fp16 operands, fp32 accum) ----------------
// One CTA = (128 q-rows, one head). 8 warps, each owns 16 q-rows.
// K/V tiles of 64 keys, double-buffered cp.async. V loaded [keys][dims] and
// re-fragmented with ldmatrix.trans. Online softmax with ex2.approx.f16x2.
__global__ __launch_bounds__(256, 2) void flash_kernel(
    const __half* __restrict__ q, const __half* __restrict__ k,
    const __half* __restrict__ v, int ldqk, __half* __restrict__ o)
{
    constexpr int PADH = 72;                 // halves per smem row (64 + 8)
    constexpr int TSZ  = 64 * PADH;          // halves
    constexpr float L2E = 1.4426950408889634f;
    extern __shared__ __half smh[];
    __half* Ks = smh;                        // [2][64][PADH]
    __half* Vs = smh + 2 * TSZ;              // [2][64][PADH]
    __half* Ps = smh + 4 * TSZ;              // [128][PADH] (Q staging, then P)

    const int tid  = threadIdx.x;
    const int wid  = tid >> 5, lane = tid & 31;
    const int gid  = lane >> 2, tig = lane & 3;
    const int h    = blockIdx.y;
    const int m0   = blockIdx.x * 128;

    // ldmatrix lane offsets (halves)
    const int aOffH = (wid * 16 + (lane & 15)) * PADH + ((lane >> 4) << 3);
    const int bOffH = (lane & 15) * PADH + ((lane >> 4) << 3);
    // trans offset for V ([j][d] tile -> B fragments of V^T)
    const int vOffH = ((lane & 7) + (((lane >> 3) & 1) << 3)) * PADH +
                      (((lane >> 4) & 1) << 3);

    // ---- stage Q tile (128 x 64 halves), extract fragments ----
    {
        uint32_t sQ = smem_u32(Ps);
        #pragma unroll
        for (int i = 0; i < 4; i++) {        // 128 rows x 8 x 16B
            int t = tid + (i << 8);
            int r = t >> 3, kq = t & 7;
            cp_async16(sQ + (uint32_t)(r * PADH + (kq << 3)) * 2,
                       q + (long long)(m0 + r) * ldqk + h * HDIM + (kq << 3));
        }
        cp_commit();
    }
    cp_wait(0);
    __syncthreads();

    uint32_t qf[4][4];
    {
        uint32_t qA = smem_u32(Ps) + aOffH * 2;
        #pragma unroll
        for (int ks = 0; ks < 4; ks++) ldsm4(qf[ks], qA + ks * 32);
    }
    __syncthreads();                         // Ps now reusable for P

    float oacc[8][4] = {};
    float m0r = -1e30f, m1r = -1e30f;
    float l0r = 0.f,    l1r = 0.f;

    auto load_tile = [&](int kt) {
        int st = kt & 1;
        uint32_t sK = smem_u32(Ks + st * TSZ);
        uint32_t sV = smem_u32(Vs + st * TSZ);
        const long long j0 = (long long)kt * KT;
        #pragma unroll
        for (int i = 0; i < 2; i++) {        // K: 64 rows x 8 x 16B
            int t = tid + (i << 8);
            int r = t >> 3, kq = t & 7;
            cp_async16(sK + (uint32_t)(r * PADH + (kq << 3)) * 2,
                       k + (j0 + r) * ldqk + h * HDIM + (kq << 3));
        }
        #pragma unroll
        for (int i = 0; i < 2; i++) {        // V: same [keys][dims] layout
            int t = tid + (i << 8);
            int r = t >> 3, kq = t & 7;
            cp_async16(sV + (uint32_t)(r * PADH + (kq << 3)) * 2,
                       v + (j0 + r) * ldqk + h * HDIM + (kq << 3));
        }
        cp_commit();
    };

    load_tile(0);

    for (int kt = 0; kt < S_LEN / KT; kt++) {
        cp_wait(0);
        __syncthreads();
        if (kt + 1 < S_LEN / KT) load_tile(kt + 1);

        const __half* Kt = Ks + (kt & 1) * TSZ;
        const __half* Vt = Vs + (kt & 1) * TSZ;

        // ---- S = Q @ K^T (16 x 64 per warp) ----
        float sacc[8][4] = {};
        {
            uint32_t kA = smem_u32(Kt) + bOffH * 2;
            #pragma unroll
            for (int ks = 0; ks < 4; ks++) {
                #pragma unroll
                for (int g = 0; g < 4; g++) {
                    uint32_t bb[4];
                    ldsm4(bb, kA + ks * 32 + g * 16 * PADH * 2);
                    mma_f16(sacc[2 * g],     qf[ks], bb[0], bb[2]);
                    mma_f16(sacc[2 * g + 1], qf[ks], bb[1], bb[3]);
                }
            }
        }

        // ---- online softmax (exp via ex2.approx.f16x2, P written as fp16) ----
        float mx0 = -1e30f, mx1 = -1e30f;
        #pragma unroll
        for (int nt = 0; nt < 8; nt++) {
            mx0 = fmaxf(mx0, fmaxf(sacc[nt][0], sacc[nt][1]));
            mx1 = fmaxf(mx1, fmaxf(sacc[nt][2], sacc[nt][3]));
        }
        mx0 = fmaxf(mx0, __shfl_xor_sync(0xffffffffu, mx0, 1));
        mx0 = fmaxf(mx0, __shfl_xor_sync(0xffffffffu, mx0, 2));
        mx1 = fmaxf(mx1, __shfl_xor_sync(0xffffffffu, mx1, 1));
        mx1 = fmaxf(mx1, __shfl_xor_sync(0xffffffffu, mx1, 2));
        float mn0 = fmaxf(m0r, mx0), mn1 = fmaxf(m1r, mx1);
        float sc0 = __expf(m0r - mn0), sc1 = __expf(m1r - mn1);
        m0r = mn0; m1r = mn1;

        float mnl0 = mn0 * L2E, mnl1 = mn1 * L2E;
        float rs0 = 0.f, rs1 = 0.f;
        __half* Pw = Ps + (wid * 16) * PADH;
        #pragma unroll
        for (int nt = 0; nt < 8; nt++) {
            int c = (nt << 3) + (tig << 1);
            __half2 t0 = __floats2half2_rn(fmaf(sacc[nt][0], L2E, -mnl0),
                                           fmaf(sacc[nt][1], L2E, -mnl0));
            __half2 t1 = __floats2half2_rn(fmaf(sacc[nt][2], L2E, -mnl1),
                                           fmaf(sacc[nt][3], L2E, -mnl1));
            uint32_t p0 = h2exp2_(*(uint32_t*)&t0);
            uint32_t p1 = h2exp2_(*(uint32_t*)&t1);
            *(uint32_t*)&Pw[gid * PADH + c]       = p0;
            *(uint32_t*)&Pw[(gid + 8) * PADH + c] = p1;
            float2 f0 = __half22float2(*(__half2*)&p0);
            float2 f1 = __half22float2(*(__half2*)&p1);
            rs0 += f0.x + f0.y;
            rs1 += f1.x + f1.y;
        }
        rs0 += __shfl_xor_sync(0xffffffffu, rs0, 1);
        rs0 += __shfl_xor_sync(0xffffffffu, rs0, 2);
        rs1 += __shfl_xor_sync(0xffffffffu, rs1, 1);
        rs1 += __shfl_xor_sync(0xffffffffu, rs1, 2);
        l0r = l0r * sc0 + rs0;
        l1r = l1r * sc1 + rs1;

        #pragma unroll
        for (int nt = 0; nt < 8; nt++) {
            oacc[nt][0] *= sc0; oacc[nt][1] *= sc0;
            oacc[nt][2] *= sc1; oacc[nt][3] *= sc1;
        }
        __syncwarp();

        // ---- refragment P via ldmatrix, O += P @ V ----
        {
            uint32_t pA = smem_u32(Ps) + aOffH * 2;
            uint32_t vA = smem_u32(Vt) + vOffH * 2;
            #pragma unroll
            for (int ks = 0; ks < 4; ks++) {     // ks over key chunks (MMA k)
                uint32_t a[4];
                ldsm4(a, pA + ks * 32);
                #pragma unroll
                for (int g = 0; g < 4; g++) {    // g over dim groups (MMA n)
                    uint32_t bb[4];
                    ldsm4t(bb, vA + (ks * 16 * PADH + g * 16) * 2);
                    mma_f16(oacc[2 * g],     a, bb[0], bb[1]);
                    mma_f16(oacc[2 * g + 1], a, bb[2], bb[3]);
                }
            }
        }
    }

    // ---- epilogue: normalize, write half ----
    float rl0 = 1.f / l0r, rl1 = 1.f / l1r;
    const int r0 = m0 + wid * 16 + gid;
    #pragma unroll
    for (int nt = 0; nt < 8; nt++) {
        int c = h * HDIM + (nt << 3) + (tig << 1);
        *(__half2*)&o[(long long)r0 * D_DIM + c] =
            __floats2half2_rn(oacc[nt][0] * rl0, oacc[nt][1] * rl0);
        *(__half2*)&o[(long long)(r0 + 8) * D_DIM + c] =
            __floats2half2_rn(oacc[nt][2] * rl1, oacc[nt][3] * rl1);
    }
}

// ---------------- fp16 mma.sync GEMM, CTA 256x128, warp tile 64x64 ----------------
// C = A[M,K]h * B[K,N]h (K-major B via ldmatrix.trans), fp32 accum.
// 8 warps (4m x 2n), 4-stage cp.async, one CTA per SM.
__global__ __launch_bounds__(256, 1) void gemm_h(
    const __half* __restrict__ A, int lda,
    const __half* __restrict__ Bkn, int ldb,
    float* __restrict__ C, __half* __restrict__ Ch, int ldc,
    int K,
    const float* __restrict__ bias,
    const float* __restrict__ resid,
    int epi)
{
    constexpr int ST   = 4;
    constexpr int PADH = 72;                 // A row: 64 + 8 halves
    constexpr int PADN = 136;                // B row: 128 + 8 halves
    constexpr int ASZ  = 256 * PADH;         // halves
    constexpr int BSZ  = 64 * PADN;
    constexpr int STH  = ASZ + BSZ;

    extern __shared__ __half smh[];
    const int tid  = threadIdx.x;
    const int wid  = tid >> 5, lane = tid & 31;
    const int gid  = lane >> 2, tig = lane & 3;
    const int wm   = wid & 3,  wn  = wid >> 2;

    A   += (long long)(blockIdx.x * 256) * lda;
    Bkn += blockIdx.y * 128;

    const int nch = K >> 6;

    // ldmatrix lane offsets (halves)
    const int aOffH = ((wm << 6) + (lane & 15)) * PADH + ((lane >> 4) << 3);
    const int bOffH = ((lane & 7) + (((lane >> 3) & 1) << 3)) * PADN +
                      (wn << 6) + (((lane >> 4) & 1) << 3);

    auto load_chunk = [&](int c) {
        __half* s = smh + (c % ST) * STH;
        const long long k0 = (long long)c << 6;
        uint32_t sA = smem_u32(s);
        #pragma unroll
        for (int i = 0; i < 8; i++) {        // A: 256 rows x 8 x 16B
            int v = tid + (i << 8);
            int r = v >> 3, kq = v & 7;
            cp_async16(sA + (uint32_t)(r * PADH + (kq << 3)) * 2,
                       A + (long long)r * lda + k0 + (kq << 3));
        }
        uint32_t sB = smem_u32(s + ASZ);
        #pragma unroll
        for (int i = 0; i < 4; i++) {        // B: 64 k-rows x 16 x 16B
            int v = tid + (i << 8);
            int r = v >> 4, cq = v & 15;
            cp_async16(sB + (uint32_t)(r * PADN + (cq << 3)) * 2,
                       Bkn + (k0 + r) * ldb + (cq << 3));
        }
        cp_commit();
    };

    float acc[4][8][4] = {};

    const int npro = (nch < ST - 1) ? nch : ST - 1;
    for (int s = 0; s < npro; s++) load_chunk(s);

    for (int c = 0; c < nch; c++) {
        int pend = nch - 1 - c;
        if (pend > ST - 2) pend = ST - 2;
        cp_wait(pend);
        __syncthreads();
        int ln = c + ST - 1;
        if (ln < nch) load_chunk(ln);

        uint32_t sbase = smem_u32(smh + (c % ST) * STH);
        uint32_t aA = sbase + aOffH * 2;
        uint32_t bA = sbase + (ASZ + bOffH) * 2;
        #pragma unroll
        for (int ks = 0; ks < 4; ks++) {     // 4 x k16
            uint32_t a[4][4];
            #pragma unroll
            for (int mt = 0; mt < 4; mt++)
                ldsm4(a[mt], aA + ks * 32 + mt * 16 * PADH * 2);
            #pragma unroll
            for (int g = 0; g < 4; g++) {    // 4 x n16
                uint32_t bb[4];
                ldsm4t(bb, bA + (ks * 16 * PADN + g * 16) * 2);
                #pragma unroll
                for (int mt = 0; mt < 4; mt++) {
                    mma_f16(acc[mt][2 * g],     a[mt], bb[0], bb[1]);
                    mma_f16(acc[mt][2 * g + 1], a[mt], bb[2], bb[3]);
                }
            }
        }
    }

    // ---------------- epilogue ----------------
    const int n0 = blockIdx.y * 128 + (wn << 6);
    const int m0 = blockIdx.x * 256 + (wm << 6);
    #pragma unroll
    for (int mt = 0; mt < 4; mt++) {
        #pragma unroll
        for (int half_ = 0; half_ < 2; half_++) {
            const int row = m0 + (mt << 4) + gid + (half_ << 3);
            const float* Rrow = resid ? (resid + (long long)row * ldc) : nullptr;
            #pragma unroll
            for (int nt = 0; nt < 8; nt++) {
                const int col = n0 + (nt << 3) + (tig << 1);
                float v0 = acc[mt][nt][(half_ << 1) + 0];
                float v1 = acc[mt][nt][(half_ << 1) + 1];
                if (epi != EPI_NONE) { v0 += bias[col]; v1 += bias[col + 1]; }
                if (epi == EPI_BIAS_RES) {
                    float2 rr = *(const float2*)(Rrow + col);
                    v0 += rr.x; v1 += rr.y;
                } else if (epi == EPI_BIAS_GELU) {
                    v0 = gelu_exact(v0); v1 = gelu_exact(v1);
                }
                if (Ch) {
                    *(__half2*)(Ch + (long long)row * ldc + col) =
                        __floats2half2_rn(v0, v1);
                } else {
                    *(float2*)(C + (long long)row * ldc + col) = make_float2(v0, v1);
                }
            }
        }
    }
}

// ---------------- launcher ----------------
extern "C" void kernel_launch(void* const* d_in, const int* in_sizes, int n_in,
                              void* d_out, int out_size)
{
    (void)in_sizes; (void)n_in; (void)out_size;
    const float* x    = (const float*)d_in[0];
    const float* ln1s = (const float*)d_in[1];
    const float* ln1b = (const float*)d_in[2];
    const float* ln2s = (const float*)d_in[3];
    const float* ln2b = (const float*)d_in[4];
    const float* Wq   = (const float*)d_in[5];
    const float* bq   = (const float*)d_in[6];
    const float* Wk   = (const float*)d_in[7];
    const float* bk   = (const float*)d_in[8];
    const float* Wv   = (const float*)d_in[9];
    const float* bv   = (const float*)d_in[10];
    const float* Wo   = (const float*)d_in[11];
    const float* bo   = (const float*)d_in[12];
    const float* W1   = (const float*)d_in[13];
    const float* b1   = (const float*)d_in[14];
    const float* W2   = (const float*)d_in[15];
    const float* b2   = (const float*)d_in[16];
    float* out = (float*)d_out;

    __half *y, *qkv, *o, *ffn, *Wqkv, *WoH, *W1H, *W2H;
    float  *x1, *bqkv;
    cudaGetSymbolAddress((void**)&y,    g_y);
    cudaGetSymbolAddress((void**)&qkv,  g_qkv);
    cudaGetSymbolAddress((void**)&o,    g_o);
    cudaGetSymbolAddress((void**)&ffn,  g_ffn);
    cudaGetSymbolAddress((void**)&Wqkv, g_Wqkv);
    cudaGetSymbolAddress((void**)&WoH,  g_WoH);
    cudaGetSymbolAddress((void**)&W1H,  g_W1H);
    cudaGetSymbolAddress((void**)&W2H,  g_W2H);
    cudaGetSymbolAddress((void**)&x1,   g_x1);
    cudaGetSymbolAddress((void**)&bqkv, g_bqkv);

    const int SMEMG  = 4 * (256 * 72 + 64 * 136) * 2;      // 217088
    const int SMEMFL = (4 * 64 * 72 + 128 * 72) * 2;       // 55296
    cudaFuncSetAttribute(gemm_h,       cudaFuncAttributeMaxDynamicSharedMemorySize, SMEMG);
    cudaFuncSetAttribute(flash_kernel, cudaFuncAttributeMaxDynamicSharedMemorySize, SMEMFL);

    // 0) LN1 -> y (half)
    ln_kernel<<<S_LEN, 256>>>(x, ln1s, ln1b, y);

    // 1-6) weight converts (layout-preserving, K-major kept)
    cvt_kernel<<<1024, 256>>>(Wq, Wqkv, D_DIM, QKV_N, 0);
    cvt_kernel<<<1024, 256>>>(Wk, Wqkv, D_DIM, QKV_N, 1024);
    cvt_kernel<<<1024, 256>>>(Wv, Wqkv, D_DIM, QKV_N, 2048);
    cvt_kernel<<<1024, 256>>>(Wo, WoH,  D_DIM, D_DIM, 0);
    cvt_kernel<<<4096, 256>>>(W1, W1H,  FF_D,  FF_D,  0);
    cvt_kernel<<<4096, 256>>>(W2, W2H,  D_DIM, D_DIM, 0);

    // 7) bias concat (fp32)
    concat3_kernel<<<QKV_N / 256, 256>>>(bq, bk, bv, bqkv);

    // 8) fused QKV projection -> qkv (half)
    gemm_h<<<dim3(S_LEN / 256, QKV_N / 128), 256, SMEMG>>>(
        y, D_DIM, Wqkv, QKV_N, nullptr, qkv, QKV_N, D_DIM, bqkv, nullptr, EPI_BIAS);

    // 9-10) RoPE (1/sqrt(HD) folded into q)
    rope_kernel<<<dim3(S_LEN, NH), 32>>>(qkv,        QKV_N, 0.125f);
    rope_kernel<<<dim3(S_LEN, NH), 32>>>(qkv + 1024, QKV_N, 1.0f);

    // 11) fused attention -> o (half); V read in-place from qkv
    flash_kernel<<<dim3(S_LEN / 128, NH), 256, SMEMFL>>>(
        qkv, qkv + 1024, qkv + 2048, QKV_N, o);

    // 12) x1 = o @ Wo + bo + x  (fp32 out)
    gemm_h<<<dim3(S_LEN / 256, D_DIM / 128), 256, SMEMG>>>(
        o, D_DIM, WoH, D_DIM, x1, nullptr, D_DIM, D_DIM, bo, x, EPI_BIAS_RES);

    // 13) LN2 -> y (half)
    ln_kernel<<<S_LEN, 256>>>(x1, ln2s, ln2b, y);

    // 14) ffn = gelu(y @ W1 + b1) (half out)
    gemm_h<<<dim3(S_LEN / 256, FF_D / 128), 256, SMEMG>>>(
        y, D_DIM, W1H, FF_D, nullptr, ffn, FF_D, D_DIM, b1, nullptr, EPI_BIAS_GELU);

    // 15) out = ffn @ W2 + b2 + x1 (fp32 out)
    gemm_h<<<dim3(S_LEN / 256, D_DIM / 128), 256, SMEMG>>>(
        ffn, FF_D, W2H, D_DIM, out, nullptr, D_DIM, FF_D, b2, x1, EPI_BIAS_RES);
}

// round 13
// speedup vs baseline: 1.1062x; 1.1062x over previous
#include <cuda_runtime.h>
#include <cuda_fp16.h>
#include <cstdint>
#include <math.h>

// Problem constants
#define S_LEN 4096
#define D_DIM 1024
#define NH    16
#define HDIM  64
#define FF_D  4096
#define KT    64
#define QKV_N 3072

#define EPI_NONE      0
#define EPI_BIAS      1
#define EPI_BIAS_RES  2
#define EPI_BIAS_GELU 3

// ---------------- scratch (device globals: allocation-free rule) ----------------
__device__ __half g_y   [S_LEN * D_DIM];
__device__ __half g_qkv [S_LEN * QKV_N];             // [S][3072]: q | k | v
__device__ __half g_o   [S_LEN * D_DIM];
__device__ __half g_ffn [(long long)S_LEN * FF_D];
__device__ __half g_Wqkv[(long long)D_DIM * QKV_N];  // [1024][3072] K-major
__device__ __half g_WoH [D_DIM * D_DIM];             // [1024][1024] K-major
__device__ __half g_W1H [(long long)D_DIM * FF_D];   // [1024][4096] K-major
__device__ __half g_W2H [(long long)FF_D * D_DIM];   // [4096][1024] K-major
__device__ float  g_x1  [S_LEN * D_DIM];
__device__ float  g_bqkv[QKV_N];

// ---------------- helpers ----------------
__device__ __forceinline__ uint32_t smem_u32(const void* p) {
    uint32_t a;
    asm("{ .reg .u64 t; cvta.to.shared.u64 t, %1; cvt.u32.u64 %0, t; }" : "=r"(a) : "l"(p));
    return a;
}
__device__ __forceinline__ void cp_async16(uint32_t s, const void* g) {
    asm volatile("cp.async.cg.shared.global [%0], [%1], 16;" :: "r"(s), "l"(g));
}
__device__ __forceinline__ void cp_commit() {
    asm volatile("cp.async.commit_group;" ::: "memory");
}
__device__ __forceinline__ void cp_wait(int n) {
    if (n == 0)      asm volatile("cp.async.wait_group 0;" ::: "memory");
    else if (n == 1) asm volatile("cp.async.wait_group 1;" ::: "memory");
    else             asm volatile("cp.async.wait_group 2;" ::: "memory");
}
__device__ __forceinline__ void ldsm4(uint32_t* r, uint32_t a) {
    asm volatile("ldmatrix.sync.aligned.m8n8.x4.shared.b16 {%0,%1,%2,%3}, [%4];"
        : "=r"(r[0]), "=r"(r[1]), "=r"(r[2]), "=r"(r[3]) : "r"(a));
}
__device__ __forceinline__ void ldsm4t(uint32_t* r, uint32_t a) {
    asm volatile("ldmatrix.sync.aligned.m8n8.x4.trans.shared.b16 {%0,%1,%2,%3}, [%4];"
        : "=r"(r[0]), "=r"(r[1]), "=r"(r[2]), "=r"(r[3]) : "r"(a));
}
__device__ __forceinline__ void mma_f16(float* c, const uint32_t* a,
                                        uint32_t b0, uint32_t b1) {
    asm volatile(
        "mma.sync.aligned.m16n8k16.row.col.f32.f16.f16.f32 "
        "{%0,%1,%2,%3}, {%4,%5,%6,%7}, {%8,%9}, {%0,%1,%2,%3};"
        : "+f"(c[0]), "+f"(c[1]), "+f"(c[2]), "+f"(c[3])
        : "r"(a[0]), "r"(a[1]), "r"(a[2]), "r"(a[3]), "r"(b0), "r"(b1));
}
__device__ __forceinline__ uint32_t h2exp2_(uint32_t x) {
    uint32_t r;
    asm("ex2.approx.f16x2 %0, %1;" : "=r"(r) : "r"(x));
    return r;
}
__device__ __forceinline__ float gelu_exact(float v) {
    return 0.5f * v * (1.0f + erff(v * 0.70710678118654752f));
}

// ---------------- LayerNorm (fp32 in, fp16 out) ----------------
__global__ __launch_bounds__(256) void ln_kernel(const float* __restrict__ x,
                                                 const float* __restrict__ sc,
                                                 const float* __restrict__ bi,
                                                 __half* __restrict__ y)
{
    long long row = blockIdx.x;
    const float* xr = x + row * D_DIM;
    int c = threadIdx.x << 2;
    float4 xv = *(const float4*)(xr + c);
    float s  = xv.x + xv.y + xv.z + xv.w;
    float ss = xv.x*xv.x + xv.y*xv.y + xv.z*xv.z + xv.w*xv.w;
    #pragma unroll
    for (int off = 16; off; off >>= 1) {
        s  += __shfl_down_sync(0xffffffffu, s,  off);
        ss += __shfl_down_sync(0xffffffffu, ss, off);
    }
    __shared__ float sbuf[8], ssbuf[8];
    __shared__ float mu_s, rinv_s;
    int w = threadIdx.x >> 5, l = threadIdx.x & 31;
    if (l == 0) { sbuf[w] = s; ssbuf[w] = ss; }
    __syncthreads();
    if (threadIdx.x == 0) {
        float S = 0.f, SS = 0.f;
        #pragma unroll
        for (int i = 0; i < 8; i++) { S += sbuf[i]; SS += ssbuf[i]; }
        float mu  = S * (1.0f / D_DIM);
        float var = SS * (1.0f / D_DIM) - mu * mu;
        mu_s = mu;
        rinv_s = rsqrtf(var + 1e-6f);
    }
    __syncthreads();
    float mu = mu_s, rinv = rinv_s;
    float4 scv = *(const float4*)(sc + c);
    float4 bv  = *(const float4*)(bi + c);
    __half2 h0 = __floats2half2_rn((xv.x - mu) * rinv * scv.x + bv.x,
                                   (xv.y - mu) * rinv * scv.y + bv.y);
    __half2 h1 = __floats2half2_rn((xv.z - mu) * rinv * scv.z + bv.z,
                                   (xv.w - mu) * rinv * scv.w + bv.w);
    uint2 pk;
    pk.x = *(uint32_t*)&h0; pk.y = *(uint32_t*)&h1;
    *(uint2*)(y + row * D_DIM + c) = pk;
}

// ---------------- RoPE (half in place; z = 0: q (scaled), z = 1: k) ----------------
__global__ void rope_kernel(__half* __restrict__ buf)
{
    int c = threadIdx.x;                 // 0..31
    int s = blockIdx.x;
    int h = blockIdx.y;
    float scale = blockIdx.z ? 1.0f : 0.125f;
    __half* p = buf + (long long)s * QKV_N + blockIdx.z * 1024 + h * HDIM;
    float freq = expf(-(float)c * (9.210340371976184f / 32.0f));
    float ang = (float)s * freq;
    float sn, cs;
    sincosf(ang, &sn, &cs);
    float x1 = __half2float(p[c]), x2 = __half2float(p[c + 32]);
    p[c]      = __float2half_rn((x1 * cs - x2 * sn) * scale);
    p[c + 32] = __float2half_rn((x2 * cs + x1 * sn) * scale);
}

// ---------------- merged prep: 6 weight converts + bias concat ----------------
// float4 segments (in units of float4):
//   [0, 262144)        Wq  -> Wqkv col 0     (1024 cols, ld 3072)
//   [262144, 524288)   Wk  -> Wqkv col 1024
//   [524288, 786432)   Wv  -> Wqkv col 2048
//   [786432, 1048576)  Wo  -> WoH            (1024 cols, ld 1024)
//   [1048576, 2097152) W1  -> W1H            (4096 cols, ld 4096)
//   [2097152, 3145728) W2  -> W2H            (1024 cols, ld 1024)
// block 12288 handles bias concat (3072 floats).
__global__ __launch_bounds__(256) void prep_kernel(
    const float* __restrict__ Wq, const float* __restrict__ Wk,
    const float* __restrict__ Wv, const float* __restrict__ Wo,
    const float* __restrict__ W1, const float* __restrict__ W2,
    const float* __restrict__ bq, const float* __restrict__ bk,
    const float* __restrict__ bv,
    __half* __restrict__ Wqkv, __half* __restrict__ WoH,
    __half* __restrict__ W1H,  __half* __restrict__ W2H,
    float* __restrict__ bqkv)
{
    if (blockIdx.x == 12288) {
        #pragma unroll
        for (int it = 0; it < 12; it++) {
            int i = it * 256 + threadIdx.x;
            bqkv[i] = (i < 1024) ? bq[i] : ((i < 2048) ? bk[i - 1024] : bv[i - 2048]);
        }
        return;
    }
    long long i4 = (long long)blockIdx.x * 256 + threadIdx.x;
    const float* in;
    __half* out;
    int nq, ldout, off;
    if (i4 < 786432) {
        int seg = (int)(i4 >> 18);               // 0,1,2
        i4 &= 262143;
        in = (seg == 0) ? Wq : (seg == 1) ? Wk : Wv;
        out = Wqkv; nq = 256; ldout = QKV_N; off = seg << 10;
    } else if (i4 < 1048576) {
        i4 -= 786432; in = Wo; out = WoH; nq = 256; ldout = D_DIM; off = 0;
    } else if (i4 < 2097152) {
        i4 -= 1048576; in = W1; out = W1H; nq = 1024; ldout = FF_D; off = 0;
    } else {
        i4 -= 2097152; in = W2; out = W2H; nq = 256; ldout = D_DIM; off = 0;
    }
    long long k = i4 / nq;
    int n = (int)(i4 % nq) << 2;
    float4 v = *(const float4*)(in + k * (nq << 2) + n);
    __half2 h0 = __floats2half2_rn(v.x, v.y);
    __half2 h1 = __floats2half2_rn(v.z, v.w);
    uint2 pk;
    pk.x = *(uint32_t*)&h0; pk.y = *(uint32_t*)&h1;
    *(uint2*)(out + k * ldout + off + n) = pk;
}

// ---------------- fused flash attention (fp16 operands, fp32 accum) ----------------
// One CTA = (128 q-rows, one head). 8 warps, each owns 16 q-rows.
// K/V tiles of 64 keys, double-buffered cp.async. V loaded [keys][dims] and
// re-fragmented with ldmatrix.trans. Online softmax with ex2.approx.f16x2.
__global__ __launch_bounds__(256, 2) void flash_kernel(
    const __half* __restrict__ q, const __half* __restrict__ k,
    const __half* __restrict__ v, int ldqk, __half* __restrict__ o)
{
    constexpr int PADH = 72;                 // halves per smem row (64 + 8)
    constexpr int TSZ  = 64 * PADH;          // halves
    constexpr float L2E = 1.4426950408889634f;
    extern __shared__ __half smh[];
    __half* Ks = smh;                        // [2][64][PADH]
    __half* Vs = smh + 2 * TSZ;              // [2][64][PADH]
    __half* Ps = smh + 4 * TSZ;              // [128][PADH] (Q staging, then P)

    const int tid  = threadIdx.x;
    const int wid  = tid >> 5, lane = tid & 31;
    const int gid  = lane >> 2, tig = lane & 3;
    const int h    = blockIdx.y;
    const int m0   = blockIdx.x * 128;

    // ldmatrix lane offsets (halves)
    const int aOffH = (wid * 16 + (lane & 15)) * PADH + ((lane >> 4) << 3);
    const int bOffH = (lane & 15) * PADH + ((lane >> 4) << 3);
    // trans offset for V ([j][d] tile -> B fragments of V^T)
    const int vOffH = ((lane & 7) + (((lane >> 3) & 1) << 3)) * PADH +
                      (((lane >> 4) & 1) << 3);

    // ---- stage Q tile (128 x 64 halves), extract fragments ----
    {
        uint32_t sQ = smem_u32(Ps);
        #pragma unroll
        for (int i = 0; i < 4; i++) {        // 128 rows x 8 x 16B
            int t = tid + (i << 8);
            int r = t >> 3, kq = t & 7;
            cp_async16(sQ + (uint32_t)(r * PADH + (kq << 3)) * 2,
                       q + (long long)(m0 + r) * ldqk + h * HDIM + (kq << 3));
        }
        cp_commit();
    }
    cp_wait(0);
    __syncthreads();

    uint32_t qf[4][4];
    {
        uint32_t qA = smem_u32(Ps) + aOffH * 2;
        #pragma unroll
        for (int ks = 0; ks < 4; ks++) ldsm4(qf[ks], qA + ks * 32);
    }
    __syncthreads();                         // Ps now reusable for P

    float oacc[8][4] = {};
    float m0r = -1e30f, m1r = -1e30f;
    float l0r = 0.f,    l1r = 0.f;

    auto load_tile = [&](int kt) {
        int st = kt & 1;
        uint32_t sK = smem_u32(Ks + st * TSZ);
        uint32_t sV = smem_u32(Vs + st * TSZ);
        const long long j0 = (long long)kt * KT;
        #pragma unroll
        for (int i = 0; i < 2; i++) {        // K: 64 rows x 8 x 16B
            int t = tid + (i << 8);
            int r = t >> 3, kq = t & 7;
            cp_async16(sK + (uint32_t)(r * PADH + (kq << 3)) * 2,
                       k + (j0 + r) * ldqk + h * HDIM + (kq << 3));
        }
        #pragma unroll
        for (int i = 0; i < 2; i++) {        // V: same [keys][dims] layout
            int t = tid + (i << 8);
            int r = t >> 3, kq = t & 7;
            cp_async16(sV + (uint32_t)(r * PADH + (kq << 3)) * 2,
                       v + (j0 + r) * ldqk + h * HDIM + (kq << 3));
        }
        cp_commit();
    };

    load_tile(0);

    for (int kt = 0; kt < S_LEN / KT; kt++) {
        cp_wait(0);
        __syncthreads();
        if (kt + 1 < S_LEN / KT) load_tile(kt + 1);

        const __half* Kt = Ks + (kt & 1) * TSZ;
        const __half* Vt = Vs + (kt & 1) * TSZ;

        // ---- S = Q @ K^T (16 x 64 per warp) ----
        float sacc[8][4] = {};
        {
            uint32_t kA = smem_u32(Kt) + bOffH * 2;
            #pragma unroll
            for (int ks = 0; ks < 4; ks++) {
                #pragma unroll
                for (int g = 0; g < 4; g++) {
                    uint32_t bb[4];
                    ldsm4(bb, kA + ks * 32 + g * 16 * PADH * 2);
                    mma_f16(sacc[2 * g],     qf[ks], bb[0], bb[2]);
                    mma_f16(sacc[2 * g + 1], qf[ks], bb[1], bb[3]);
                }
            }
        }

        // ---- online softmax (exp via ex2.approx.f16x2, P written as fp16) ----
        float mx0 = -1e30f, mx1 = -1e30f;
        #pragma unroll
        for (int nt = 0; nt < 8; nt++) {
            mx0 = fmaxf(mx0, fmaxf(sacc[nt][0], sacc[nt][1]));
            mx1 = fmaxf(mx1, fmaxf(sacc[nt][2], sacc[nt][3]));
        }
        mx0 = fmaxf(mx0, __shfl_xor_sync(0xffffffffu, mx0, 1));
        mx0 = fmaxf(mx0, __shfl_xor_sync(0xffffffffu, mx0, 2));
        mx1 = fmaxf(mx1, __shfl_xor_sync(0xffffffffu, mx1, 1));
        mx1 = fmaxf(mx1, __shfl_xor_sync(0xffffffffu, mx1, 2));
        float mn0 = fmaxf(m0r, mx0), mn1 = fmaxf(m1r, mx1);
        float sc0 = __expf(m0r - mn0), sc1 = __expf(m1r - mn1);
        m0r = mn0; m1r = mn1;

        float mnl0 = mn0 * L2E, mnl1 = mn1 * L2E;
        float rs0 = 0.f, rs1 = 0.f;
        __half* Pw = Ps + (wid * 16) * PADH;
        #pragma unroll
        for (int nt = 0; nt < 8; nt++) {
            int c = (nt << 3) + (tig << 1);
            __half2 t0 = __floats2half2_rn(fmaf(sacc[nt][0], L2E, -mnl0),
                                           fmaf(sacc[nt][1], L2E, -mnl0));
            __half2 t1 = __floats2half2_rn(fmaf(sacc[nt][2], L2E, -mnl1),
                                           fmaf(sacc[nt][3], L2E, -mnl1));
            uint32_t p0 = h2exp2_(*(uint32_t*)&t0);
            uint32_t p1 = h2exp2_(*(uint32_t*)&t1);
            *(uint32_t*)&Pw[gid * PADH + c]       = p0;
            *(uint32_t*)&Pw[(gid + 8) * PADH + c] = p1;
            float2 f0 = __half22float2(*(__half2*)&p0);
            float2 f1 = __half22float2(*(__half2*)&p1);
            rs0 += f0.x + f0.y;
            rs1 += f1.x + f1.y;
        }
        rs0 += __shfl_xor_sync(0xffffffffu, rs0, 1);
        rs0 += __shfl_xor_sync(0xffffffffu, rs0, 2);
        rs1 += __shfl_xor_sync(0xffffffffu, rs1, 1);
        rs1 += __shfl_xor_sync(0xffffffffu, rs1, 2);
        l0r = l0r * sc0 + rs0;
        l1r = l1r * sc1 + rs1;

        #pragma unroll
        for (int nt = 0; nt < 8; nt++) {
            oacc[nt][0] *= sc0; oacc[nt][1] *= sc0;
            oacc[nt][2] *= sc1; oacc[nt][3] *= sc1;
        }
        __syncwarp();

        // ---- refragment P via ldmatrix, O += P @ V ----
        {
            uint32_t pA = smem_u32(Ps) + aOffH * 2;
            uint32_t vA = smem_u32(Vt) + vOffH * 2;
            #pragma unroll
            for (int ks = 0; ks < 4; ks++) {     // ks over key chunks (MMA k)
                uint32_t a[4];
                ldsm4(a, pA + ks * 32);
                #pragma unroll
                for (int g = 0; g < 4; g++) {    // g over dim groups (MMA n)
                    uint32_t bb[4];
                    ldsm4t(bb, vA + (ks * 16 * PADH + g * 16) * 2);
                    mma_f16(oacc[2 * g],     a, bb[0], bb[1]);
                    mma_f16(oacc[2 * g + 1], a, bb[2], bb[3]);
                }
            }
        }
    }

    // ---- epilogue: normalize, write half ----
    float rl0 = 1.f / l0r, rl1 = 1.f / l1r;
    const int r0 = m0 + wid * 16 + gid;
    #pragma unroll
    for (int nt = 0; nt < 8; nt++) {
        int c = h * HDIM + (nt << 3) + (tig << 1);
        *(__half2*)&o[(long long)r0 * D_DIM + c] =
            __floats2half2_rn(oacc[nt][0] * rl0, oacc[nt][1] * rl0);
        *(__half2*)&o[(long long)(r0 + 8) * D_DIM + c] =
            __floats2half2_rn(oacc[nt][2] * rl1, oacc[nt][3] * rl1);
    }
}

// ---------------- fp16 mma.sync GEMM (R10 winner), B K-major via ldmatrix.trans ----
// C[128x128 tile] = A[M,K]h * B[K,N]h, fp32 accum. 8 warps (4m x 2n), warp 32x64.
__global__ __launch_bounds__(256, 2) void gemm_h(
    const __half* __restrict__ A, int lda,
    const __half* __restrict__ Bkn, int ldb,
    float* __restrict__ C, __half* __restrict__ Ch, int ldc,
    int K,
    const float* __restrict__ bias,
    const float* __restrict__ resid,
    int epi)
{
    constexpr int ST   = 3;
    constexpr int PADH = 72;                 // A row: 64 + 8 halves
    constexpr int PADN = 136;                // B row: 128 + 8 halves
    constexpr int ASZ  = 128 * PADH;         // halves
    constexpr int BSZ  = 64 * PADN;
    constexpr int STH  = ASZ + BSZ;

    extern __shared__ __half smh[];
    const int tid  = threadIdx.x;
    const int wid  = tid >> 5, lane = tid & 31;
    const int gid  = lane >> 2, tig = lane & 3;
    const int wm   = wid & 3,  wn  = wid >> 2;

    A   += (long long)(blockIdx.x * 128) * lda;
    Bkn += blockIdx.y * 128;

    const int nch = K >> 6;

    // ldmatrix lane offsets (halves)
    const int aOffH = ((wm << 5) + (lane & 15)) * PADH + ((lane >> 4) << 3);
    const int bOffH = ((lane & 7) + (((lane >> 3) & 1) << 3)) * PADN +
                      (wn << 6) + (((lane >> 4) & 1) << 3);

    auto load_chunk = [&](int c) {
        __half* s = smh + (c % ST) * STH;
        const long long k0 = (long long)c << 6;
        uint32_t sA = smem_u32(s);
        #pragma unroll
        for (int i = 0; i < 4; i++) {        // A: 128 rows x 8 x 16B
            int v = tid + (i << 8);
            int r = v >> 3, kq = v & 7;
            cp_async16(sA + (uint32_t)(r * PADH + (kq << 3)) * 2,
                       A + (long long)r * lda + k0 + (kq << 3));
        }
        uint32_t sB = smem_u32(s + ASZ);
        #pragma unroll
        for (int i = 0; i < 4; i++) {        // B: 64 k-rows x 16 x 16B
            int v = tid + (i << 8);
            int r = v >> 4, cq = v & 15;
            cp_async16(sB + (uint32_t)(r * PADN + (cq << 3)) * 2,
                       Bkn + (k0 + r) * ldb + (cq << 3));
        }
        cp_commit();
    };

    float acc[2][8][4] = {};

    const int npro = (nch < ST - 1) ? nch : ST - 1;
    for (int s = 0; s < npro; s++) load_chunk(s);

    for (int c = 0; c < nch; c++) {
        int pend = nch - 1 - c;
        if (pend > ST - 2) pend = ST - 2;
        cp_wait(pend);
        __syncthreads();
        int ln = c + ST - 1;
        if (ln < nch) load_chunk(ln);

        uint32_t sbase = smem_u32(smh + (c % ST) * STH);
        uint32_t aA = sbase + aOffH * 2;
        uint32_t bA = sbase + (ASZ + bOffH) * 2;
        #pragma unroll
        for (int ks = 0; ks < 4; ks++) {     // 4 x k16
            uint32_t a0[4], a1[4];
            ldsm4(a0, aA + ks * 32);
            ldsm4(a1, aA + ks * 32 + 16 * PADH * 2);
            #pragma unroll
            for (int g = 0; g < 4; g++) {    // 4 x n16
                uint32_t bb[4];
                ldsm4t(bb, bA + (ks * 16 * PADN + g * 16) * 2);
                mma_f16(acc[0][2 * g],     a0, bb[0], bb[1]);
                mma_f16(acc[0][2 * g + 1], a0, bb[2], bb[3]);
                mma_f16(acc[1][2 * g],     a1, bb[0], bb[1]);
                mma_f16(acc[1][2 * g + 1], a1, bb[2], bb[3]);
            }
        }
    }

    // ---------------- epilogue ----------------
    const int n0 = blockIdx.y * 128 + (wn << 6);
    const int m0 = blockIdx.x * 128 + (wm << 5);
    #pragma unroll
    for (int mt = 0; mt < 2; mt++) {
        #pragma unroll
        for (int half_ = 0; half_ < 2; half_++) {
            const int row = m0 + (mt << 4) + gid + (half_ << 3);
            const float* Rrow = resid ? (resid + (long long)row * ldc) : nullptr;
            #pragma unroll
            for (int nt = 0; nt < 8; nt++) {
                const int col = n0 + (nt << 3) + (tig << 1);
                float v0 = acc[mt][nt][(half_ << 1) + 0];
                float v1 = acc[mt][nt][(half_ << 1) + 1];
                if (epi != EPI_NONE) { v0 += bias[col]; v1 += bias[col + 1]; }
                if (epi == EPI_BIAS_RES) {
                    float2 rr = *(const float2*)(Rrow + col);
                    v0 += rr.x; v1 += rr.y;
                } else if (epi == EPI_BIAS_GELU) {
                    v0 = gelu_exact(v0); v1 = gelu_exact(v1);
                }
                if (Ch) {
                    *(__half2*)(Ch + (long long)row * ldc + col) =
                        __floats2half2_rn(v0, v1);
                } else {
                    *(float2*)(C + (long long)row * ldc + col) = make_float2(v0, v1);
                }
            }
        }
    }
}

// ---------------- launcher ----------------
extern "C" void kernel_launch(void* const* d_in, const int* in_sizes, int n_in,
                              void* d_out, int out_size)
{
    (void)in_sizes; (void)n_in; (void)out_size;
    const float* x    = (const float*)d_in[0];
    const float* ln1s = (const float*)d_in[1];
    const float* ln1b = (const float*)d_in[2];
    const float* ln2s = (const float*)d_in[3];
    const float* ln2b = (const float*)d_in[4];
    const float* Wq   = (const float*)d_in[5];
    const float* bq   = (const float*)d_in[6];
    const float* Wk   = (const float*)d_in[7];
    const float* bk   = (const float*)d_in[8];
    const float* Wv   = (const float*)d_in[9];
    const float* bv   = (const float*)d_in[10];
    const float* Wo   = (const float*)d_in[11];
    const float* bo   = (const float*)d_in[12];
    const float* W1   = (const float*)d_in[13];
    const float* b1   = (const float*)d_in[14];
    const float* W2   = (const float*)d_in[15];
    const float* b2   = (const float*)d_in[16];
    float* out = (float*)d_out;

    __half *y, *qkv, *o, *ffn, *Wqkv, *WoH, *W1H, *W2H;
    float  *x1, *bqkv;
    cudaGetSymbolAddress((void**)&y,    g_y);
    cudaGetSymbolAddress((void**)&qkv,  g_qkv);
    cudaGetSymbolAddress((void**)&o,    g_o);
    cudaGetSymbolAddress((void**)&ffn,  g_ffn);
    cudaGetSymbolAddress((void**)&Wqkv, g_Wqkv);
    cudaGetSymbolAddress((void**)&WoH,  g_WoH);
    cudaGetSymbolAddress((void**)&W1H,  g_W1H);
    cudaGetSymbolAddress((void**)&W2H,  g_W2H);
    cudaGetSymbolAddress((void**)&x1,   g_x1);
    cudaGetSymbolAddress((void**)&bqkv, g_bqkv);

    const int SMEMG  = 3 * (128 * 72 + 64 * 136) * 2;      // 107520
    const int SMEMFL = (4 * 64 * 72 + 128 * 72) * 2;       // 55296
    cudaFuncSetAttribute(gemm_h,       cudaFuncAttributeMaxDynamicSharedMemorySize, SMEMG);
    cudaFuncSetAttribute(flash_kernel, cudaFuncAttributeMaxDynamicSharedMemorySize, SMEMFL);

    // 0) LN1 -> y (half)
    ln_kernel<<<S_LEN, 256>>>(x, ln1s, ln1b, y);

    // 1) merged weight converts + bias concat
    prep_kernel<<<12289, 256>>>(Wq, Wk, Wv, Wo, W1, W2, bq, bk, bv,
                                Wqkv, WoH, W1H, W2H, bqkv);

    // 2) fused QKV projection -> qkv (half)
    gemm_h<<<dim3(S_LEN / 128, QKV_N / 128), 256, SMEMG>>>(
        y, D_DIM, Wqkv, QKV_N, nullptr, qkv, QKV_N, D_DIM, bqkv, nullptr, EPI_BIAS);

    // 3) RoPE on q and k (z = 0: q with 1/sqrt(HD); z = 1: k)
    rope_kernel<<<dim3(S_LEN, NH, 2), 32>>>(qkv);

    // 4) fused attention -> o (half); V read in-place from qkv
    flash_kernel<<<dim3(S_LEN / 128, NH), 256, SMEMFL>>>(
        qkv, qkv + 1024, qkv + 2048, QKV_N, o);

    // 5) x1 = o @ Wo + bo + x  (fp32 out)
    gemm_h<<<dim3(S_LEN / 128, D_DIM / 128), 256, SMEMG>>>(
        o, D_DIM, WoH, D_DIM, x1, nullptr, D_DIM, D_DIM, bo, x, EPI_BIAS_RES);

    // 6) LN2 -> y (half)
    ln_kernel<<<S_LEN, 256>>>(x1, ln2s, ln2b, y);

    // 7) ffn = gelu(y @ W1 + b1) (half out)
    gemm_h<<<dim3(S_LEN / 128, FF_D / 128), 256, SMEMG>>>(
        y, D_DIM, W1H, FF_D, nullptr, ffn, FF_D, D_DIM, b1, nullptr, EPI_BIAS_GELU);

    // 8) out = ffn @ W2 + b2 + x1 (fp32 out)
    gemm_h<<<dim3(S_LEN / 128, D_DIM / 128), 256, SMEMG>>>(
        ffn, FF_D, W2H, D_DIM, out, nullptr, D_DIM, FF_D, b2, x1, EPI_BIAS_RES);
}

// round 15
// speedup vs baseline: 1.2074x; 1.0915x over previous
#include <cuda_runtime.h>
#include <cuda_fp16.h>
#include <cstdint>
#include <math.h>

// Problem constants
#define S_LEN 4096
#define D_DIM 1024
#define NH    16
#define HDIM  64
#define KT    64
#define FF_D  4096
#define QKV_N 3072

#define EPI_NONE      0
#define EPI_BIAS      1
#define EPI_BIAS_RES  2
#define EPI_BIAS_GELU 3

// ---------------- scratch (device globals: allocation-free rule) ----------------
__device__ __half g_y   [S_LEN * D_DIM];
__device__ __half g_qkv [S_LEN * QKV_N];             // [S][3072]: q | k | v
__device__ __half g_o   [S_LEN * D_DIM];
__device__ __half g_ffn [(long long)S_LEN * FF_D];
__device__ __half g_Wqkv[(long long)D_DIM * QKV_N];  // [1024][3072] K-major
__device__ __half g_WoH [D_DIM * D_DIM];             // [1024][1024] K-major
__device__ __half g_W1H [(long long)D_DIM * FF_D];   // [1024][4096] K-major
__device__ __half g_W2H [(long long)FF_D * D_DIM];   // [4096][1024] K-major
__device__ float  g_x1  [S_LEN * D_DIM];
__device__ float  g_bqkv[QKV_N];

// ---------------- helpers ----------------
__device__ __forceinline__ uint32_t smem_u32(const void* p) {
    uint32_t a;
    asm("{ .reg .u64 t; cvta.to.shared.u64 t, %1; cvt.u32.u64 %0, t; }" : "=r"(a) : "l"(p));
    return a;
}
__device__ __forceinline__ void cp_async16(uint32_t s, const void* g) {
    asm volatile("cp.async.cg.shared.global [%0], [%1], 16;" :: "r"(s), "l"(g));
}
__device__ __forceinline__ void cp_commit() {
    asm volatile("cp.async.commit_group;" ::: "memory");
}
__device__ __forceinline__ void cp_wait(int n) {
    if (n == 0)      asm volatile("cp.async.wait_group 0;" ::: "memory");
    else if (n == 1) asm volatile("cp.async.wait_group 1;" ::: "memory");
    else             asm volatile("cp.async.wait_group 2;" ::: "memory");
}
__device__ __forceinline__ void ldsm4(uint32_t* r, uint32_t a) {
    asm volatile("ldmatrix.sync.aligned.m8n8.x4.shared.b16 {%0,%1,%2,%3}, [%4];"
        : "=r"(r[0]), "=r"(r[1]), "=r"(r[2]), "=r"(r[3]) : "r"(a));
}
__device__ __forceinline__ void ldsm4t(uint32_t* r, uint32_t a) {
    asm volatile("ldmatrix.sync.aligned.m8n8.x4.trans.shared.b16 {%0,%1,%2,%3}, [%4];"
        : "=r"(r[0]), "=r"(r[1]), "=r"(r[2]), "=r"(r[3]) : "r"(a));
}
__device__ __forceinline__ void mma_f16(float* c, const uint32_t* a,
                                        uint32_t b0, uint32_t b1) {
    asm volatile(
        "mma.sync.aligned.m16n8k16.row.col.f32.f16.f16.f32 "
        "{%0,%1,%2,%3}, {%4,%5,%6,%7}, {%8,%9}, {%0,%1,%2,%3};"
        : "+f"(c[0]), "+f"(c[1]), "+f"(c[2]), "+f"(c[3])
        : "r"(a[0]), "r"(a[1]), "r"(a[2]), "r"(a[3]), "r"(b0), "r"(b1));
}
__device__ __forceinline__ uint32_t h2exp2_(uint32_t x) {
    uint32_t r;
    asm("ex2.approx.f16x2 %0, %1;" : "=r"(r) : "r"(x));
    return r;
}
__device__ __forceinline__ float gelu_exact(float v) {
    return 0.5f * v * (1.0f + erff(v * 0.70710678118654752f));
}

// ---------------- LayerNorm (fp32 in, fp16 out) ----------------
__global__ __launch_bounds__(256) void ln_kernel(const float* __restrict__ x,
                                                 const float* __restrict__ sc,
                                                 const float* __restrict__ bi,
                                                 __half* __restrict__ y)
{
    long long row = blockIdx.x;
    const float* xr = x + row * D_DIM;
    int c = threadIdx.x << 2;
    float4 xv = *(const float4*)(xr + c);
    float s  = xv.x + xv.y + xv.z + xv.w;
    float ss = xv.x*xv.x + xv.y*xv.y + xv.z*xv.z + xv.w*xv.w;
    #pragma unroll
    for (int off = 16; off; off >>= 1) {
        s  += __shfl_down_sync(0xffffffffu, s,  off);
        ss += __shfl_down_sync(0xffffffffu, ss, off);
    }
    __shared__ float sbuf[8], ssbuf[8];
    __shared__ float mu_s, rinv_s;
    int w = threadIdx.x >> 5, l = threadIdx.x & 31;
    if (l == 0) { sbuf[w] = s; ssbuf[w] = ss; }
    __syncthreads();
    if (threadIdx.x == 0) {
        float S = 0.f, SS = 0.f;
        #pragma unroll
        for (int i = 0; i < 8; i++) { S += sbuf[i]; SS += ssbuf[i]; }
        float mu  = S * (1.0f / D_DIM);
        float var = SS * (1.0f / D_DIM) - mu * mu;
        mu_s = mu;
        rinv_s = rsqrtf(var + 1e-6f);
    }
    __syncthreads();
    float mu = mu_s, rinv = rinv_s;
    float4 scv = *(const float4*)(sc + c);
    float4 bv  = *(const float4*)(bi + c);
    __half2 h0 = __floats2half2_rn((xv.x - mu) * rinv * scv.x + bv.x,
                                   (xv.y - mu) * rinv * scv.y + bv.y);
    __half2 h1 = __floats2half2_rn((xv.z - mu) * rinv * scv.z + bv.z,
                                   (xv.w - mu) * rinv * scv.w + bv.w);
    uint2 pk;
    pk.x = *(uint32_t*)&h0; pk.y = *(uint32_t*)&h1;
    *(uint2*)(y + row * D_DIM + c) = pk;
}

// ---------------- RoPE: one warp per token, angles computed once, 16h x {q,k} ----
// thread (s, c): sincos once; apply to q (scaled by 1/sqrt(HD)) and k, all heads.
__global__ __launch_bounds__(256) void rope_kernel(__half* __restrict__ qkv)
{
    int idx = blockIdx.x * 256 + threadIdx.x;    // 4096*32 threads
    int s = idx >> 5, c = idx & 31;
    float freq = expf(-(float)c * (9.210340371976184f / 32.0f));
    float ang = (float)s * freq;
    float sn, cs;
    sincosf(ang, &sn, &cs);
    __half* base = qkv + (long long)s * QKV_N;
    #pragma unroll
    for (int h = 0; h < NH; h++) {
        __half* pq = base + h * HDIM;
        float q1 = __half2float(pq[c]), q2 = __half2float(pq[c + 32]);
        pq[c]      = __float2half_rn((q1 * cs - q2 * sn) * 0.125f);
        pq[c + 32] = __float2half_rn((q2 * cs + q1 * sn) * 0.125f);
        __half* pk = base + 1024 + h * HDIM;
        float k1 = __half2float(pk[c]), k2 = __half2float(pk[c + 32]);
        pk[c]      = __float2half_rn(k1 * cs - k2 * sn);
        pk[c + 32] = __float2half_rn(k2 * cs + k1 * sn);
    }
}

// ---------------- merged prep: 6 weight converts + bias concat ----------------
__global__ __launch_bounds__(256) void prep_kernel(
    const float* __restrict__ Wq, const float* __restrict__ Wk,
    const float* __restrict__ Wv, const float* __restrict__ Wo,
    const float* __restrict__ W1, const float* __restrict__ W2,
    const float* __restrict__ bq, const float* __restrict__ bk,
    const float* __restrict__ bv,
    __half* __restrict__ Wqkv, __half* __restrict__ WoH,
    __half* __restrict__ W1H,  __half* __restrict__ W2H,
    float* __restrict__ bqkv)
{
    if (blockIdx.x == 12288) {
        #pragma unroll
        for (int it = 0; it < 12; it++) {
            int i = it * 256 + threadIdx.x;
            bqkv[i] = (i < 1024) ? bq[i] : ((i < 2048) ? bk[i - 1024] : bv[i - 2048]);
        }
        return;
    }
    long long i4 = (long long)blockIdx.x * 256 + threadIdx.x;
    const float* in;
    __half* out;
    int nq, ldout, off;
    if (i4 < 786432) {
        int seg = (int)(i4 >> 18);               // 0,1,2
        i4 &= 262143;
        in = (seg == 0) ? Wq : (seg == 1) ? Wk : Wv;
        out = Wqkv; nq = 256; ldout = QKV_N; off = seg << 10;
    } else if (i4 < 1048576) {
        i4 -= 786432; in = Wo; out = WoH; nq = 256; ldout = D_DIM; off = 0;
    } else if (i4 < 2097152) {
        i4 -= 1048576; in = W1; out = W1H; nq = 1024; ldout = FF_D; off = 0;
    } else {
        i4 -= 2097152; in = W2; out = W2H; nq = 256; ldout = D_DIM; off = 0;
    }
    long long k = i4 / nq;
    int n = (int)(i4 % nq) << 2;
    float4 v = *(const float4*)(in + k * (nq << 2) + n);
    __half2 h0 = __floats2half2_rn(v.x, v.y);
    __half2 h1 = __floats2half2_rn(v.z, v.w);
    uint2 pk;
    pk.x = *(uint32_t*)&h0; pk.y = *(uint32_t*)&h1;
    *(uint2*)(out + k * ldout + off + n) = pk;
}

// ---------------- fused flash attention (fp16 operands, fp32 accum) ----------------
// One CTA = (128 q-rows, one head). 8 warps, each owns 16 q-rows.
// K/V tiles of 64 keys, double-buffered cp.async. V loaded [keys][dims] and
// re-fragmented with ldmatrix.trans. Online softmax with ex2.approx.f16x2.
__global__ __launch_bounds__(256, 2) void flash_kernel(
    const __half* __restrict__ q, const __half* __restrict__ k,
    const __half* __restrict__ v, int ldqk, __half* __restrict__ o)
{
    constexpr int PADH = 72;                 // halves per smem row (64 + 8)
    constexpr int TSZ  = 64 * PADH;          // halves
    constexpr float L2E = 1.4426950408889634f;
    extern __shared__ __half smh[];
    __half* Ks = smh;                        // [2][64][PADH]
    __half* Vs = smh + 2 * TSZ;              // [2][64][PADH]
    __half* Ps = smh + 4 * TSZ;              // [128][PADH] (Q staging, then P)

    const int tid  = threadIdx.x;
    const int wid  = tid >> 5, lane = tid & 31;
    const int gid  = lane >> 2, tig = lane & 3;
    const int h    = blockIdx.y;
    const int m0   = blockIdx.x * 128;

    // ldmatrix lane offsets (halves)
    const int aOffH = (wid * 16 + (lane & 15)) * PADH + ((lane >> 4) << 3);
    const int bOffH = (lane & 15) * PADH + ((lane >> 4) << 3);
    // trans offset for V ([j][d] tile -> B fragments of V^T)
    const int vOffH = ((lane & 7) + (((lane >> 3) & 1) << 3)) * PADH +
                      (((lane >> 4) & 1) << 3);

    // ---- stage Q tile (128 x 64 halves), extract fragments ----
    {
        uint32_t sQ = smem_u32(Ps);
        #pragma unroll
        for (int i = 0; i < 4; i++) {        // 128 rows x 8 x 16B
            int t = tid + (i << 8);
            int r = t >> 3, kq = t & 7;
            cp_async16(sQ + (uint32_t)(r * PADH + (kq << 3)) * 2,
                       q + (long long)(m0 + r) * ldqk + h * HDIM + (kq << 3));
        }
        cp_commit();
    }
    cp_wait(0);
    __syncthreads();

    uint32_t qf[4][4];
    {
        uint32_t qA = smem_u32(Ps) + aOffH * 2;
        #pragma unroll
        for (int ks = 0; ks < 4; ks++) ldsm4(qf[ks], qA + ks * 32);
    }
    __syncthreads();                         // Ps now reusable for P

    float oacc[8][4] = {};
    float m0r = -1e30f, m1r = -1e30f;
    float l0r = 0.f,    l1r = 0.f;

    auto load_tile = [&](int kt) {
        int st = kt & 1;
        uint32_t sK = smem_u32(Ks + st * TSZ);
        uint32_t sV = smem_u32(Vs + st * TSZ);
        const long long j0 = (long long)kt * KT;
        #pragma unroll
        for (int i = 0; i < 2; i++) {        // K: 64 rows x 8 x 16B
            int t = tid + (i << 8);
            int r = t >> 3, kq = t & 7;
            cp_async16(sK + (uint32_t)(r * PADH + (kq << 3)) * 2,
                       k + (j0 + r) * ldqk + h * HDIM + (kq << 3));
        }
        #pragma unroll
        for (int i = 0; i < 2; i++) {        // V: same [keys][dims] layout
            int t = tid + (i << 8);
            int r = t >> 3, kq = t & 7;
            cp_async16(sV + (uint32_t)(r * PADH + (kq << 3)) * 2,
                       v + (j0 + r) * ldqk + h * HDIM + (kq << 3));
        }
        cp_commit();
    };

    load_tile(0);

    for (int kt = 0; kt < S_LEN / KT; kt++) {
        cp_wait(0);
        __syncthreads();
        if (kt + 1 < S_LEN / KT) load_tile(kt + 1);

        const __half* Kt = Ks + (kt & 1) * TSZ;
        const __half* Vt = Vs + (kt & 1) * TSZ;

        // ---- S = Q @ K^T (16 x 64 per warp) ----
        float sacc[8][4] = {};
        {
            uint32_t kA = smem_u32(Kt) + bOffH * 2;
            #pragma unroll
            for (int ks = 0; ks < 4; ks++) {
                #pragma unroll
                for (int g = 0; g < 4; g++) {
                    uint32_t bb[4];
                    ldsm4(bb, kA + ks * 32 + g * 16 * PADH * 2);
                    mma_f16(sacc[2 * g],     qf[ks], bb[0], bb[2]);
                    mma_f16(sacc[2 * g + 1], qf[ks], bb[1], bb[3]);
                }
            }
        }

        // ---- online softmax (exp via ex2.approx.f16x2, P written as fp16) ----
        float mx0 = -1e30f, mx1 = -1e30f;
        #pragma unroll
        for (int nt = 0; nt < 8; nt++) {
            mx0 = fmaxf(mx0, fmaxf(sacc[nt][0], sacc[nt][1]));
            mx1 = fmaxf(mx1, fmaxf(sacc[nt][2], sacc[nt][3]));
        }
        mx0 = fmaxf(mx0, __shfl_xor_sync(0xffffffffu, mx0, 1));
        mx0 = fmaxf(mx0, __shfl_xor_sync(0xffffffffu, mx0, 2));
        mx1 = fmaxf(mx1, __shfl_xor_sync(0xffffffffu, mx1, 1));
        mx1 = fmaxf(mx1, __shfl_xor_sync(0xffffffffu, mx1, 2));
        float mn0 = fmaxf(m0r, mx0), mn1 = fmaxf(m1r, mx1);
        float sc0 = __expf(m0r - mn0), sc1 = __expf(m1r - mn1);
        m0r = mn0; m1r = mn1;

        float mnl0 = mn0 * L2E, mnl1 = mn1 * L2E;
        float rs0 = 0.f, rs1 = 0.f;
        __half* Pw = Ps + (wid * 16) * PADH;
        #pragma unroll
        for (int nt = 0; nt < 8; nt++) {
            int c = (nt << 3) + (tig << 1);
            __half2 t0 = __floats2half2_rn(fmaf(sacc[nt][0], L2E, -mnl0),
                                           fmaf(sacc[nt][1], L2E, -mnl0));
            __half2 t1 = __floats2half2_rn(fmaf(sacc[nt][2], L2E, -mnl1),
                                           fmaf(sacc[nt][3], L2E, -mnl1));
            uint32_t p0 = h2exp2_(*(uint32_t*)&t0);
            uint32_t p1 = h2exp2_(*(uint32_t*)&t1);
            *(uint32_t*)&Pw[gid * PADH + c]       = p0;
            *(uint32_t*)&Pw[(gid + 8) * PADH + c] = p1;
            float2 f0 = __half22float2(*(__half2*)&p0);
            float2 f1 = __half22float2(*(__half2*)&p1);
            rs0 += f0.x + f0.y;
            rs1 += f1.x + f1.y;
        }
        rs0 += __shfl_xor_sync(0xffffffffu, rs0, 1);
        rs0 += __shfl_xor_sync(0xffffffffu, rs0, 2);
        rs1 += __shfl_xor_sync(0xffffffffu, rs1, 1);
        rs1 += __shfl_xor_sync(0xffffffffu, rs1, 2);
        l0r = l0r * sc0 + rs0;
        l1r = l1r * sc1 + rs1;

        #pragma unroll
        for (int nt = 0; nt < 8; nt++) {
            oacc[nt][0] *= sc0; oacc[nt][1] *= sc0;
            oacc[nt][2] *= sc1; oacc[nt][3] *= sc1;
        }
        __syncwarp();

        // ---- refragment P via ldmatrix, O += P @ V ----
        {
            uint32_t pA = smem_u32(Ps) + aOffH * 2;
            uint32_t vA = smem_u32(Vt) + vOffH * 2;
            #pragma unroll
            for (int ks = 0; ks < 4; ks++) {     // ks over key chunks (MMA k)
                uint32_t a[4];
                ldsm4(a, pA + ks * 32);
                #pragma unroll
                for (int g = 0; g < 4; g++) {    // g over dim groups (MMA n)
                    uint32_t bb[4];
                    ldsm4t(bb, vA + (ks * 16 * PADH + g * 16) * 2);
                    mma_f16(oacc[2 * g],     a, bb[0], bb[1]);
                    mma_f16(oacc[2 * g + 1], a, bb[2], bb[3]);
                }
            }
        }
    }

    // ---- epilogue: normalize, write half ----
    float rl0 = 1.f / l0r, rl1 = 1.f / l1r;
    const int r0 = m0 + wid * 16 + gid;
    #pragma unroll
    for (int nt = 0; nt < 8; nt++) {
        int c = h * HDIM + (nt << 3) + (tig << 1);
        *(__half2*)&o[(long long)r0 * D_DIM + c] =
            __floats2half2_rn(oacc[nt][0] * rl0, oacc[nt][1] * rl0);
        *(__half2*)&o[(long long)(r0 + 8) * D_DIM + c] =
            __floats2half2_rn(oacc[nt][2] * rl1, oacc[nt][3] * rl1);
    }
}

// ---------------- fp16 mma.sync GEMM (R10 winner), B K-major via ldmatrix.trans ----
// C[128x128 tile] = A[M,K]h * B[K,N]h, fp32 accum. 8 warps (4m x 2n), warp 32x64.
__global__ __launch_bounds__(256, 2) void gemm_h(
    const __half* __restrict__ A, int lda,
    const __half* __restrict__ Bkn, int ldb,
    float* __restrict__ C, __half* __restrict__ Ch, int ldc,
    int K,
    const float* __restrict__ bias,
    const float* __restrict__ resid,
    int epi)
{
    constexpr int ST   = 3;
    constexpr int PADH = 72;                 // A row: 64 + 8 halves
    constexpr int PADN = 136;                // B row: 128 + 8 halves
    constexpr int ASZ  = 128 * PADH;         // halves
    constexpr int BSZ  = 64 * PADN;
    constexpr int STH  = ASZ + BSZ;

    extern __shared__ __half smh[];
    const int tid  = threadIdx.x;
    const int wid  = tid >> 5, lane = tid & 31;
    const int gid  = lane >> 2, tig = lane & 3;
    const int wm   = wid & 3,  wn  = wid >> 2;

    A   += (long long)(blockIdx.x * 128) * lda;
    Bkn += blockIdx.y * 128;

    const int nch = K >> 6;

    // ldmatrix lane offsets (halves)
    const int aOffH = ((wm << 5) + (lane & 15)) * PADH + ((lane >> 4) << 3);
    const int bOffH = ((lane & 7) + (((lane >> 3) & 1) << 3)) * PADN +
                      (wn << 6) + (((lane >> 4) & 1) << 3);

    auto load_chunk = [&](int c) {
        __half* s = smh + (c % ST) * STH;
        const long long k0 = (long long)c << 6;
        uint32_t sA = smem_u32(s);
        #pragma unroll
        for (int i = 0; i < 4; i++) {        // A: 128 rows x 8 x 16B
            int v = tid + (i << 8);
            int r = v >> 3, kq = v & 7;
            cp_async16(sA + (uint32_t)(r * PADH + (kq << 3)) * 2,
                       A + (long long)r * lda + k0 + (kq << 3));
        }
        uint32_t sB = smem_u32(s + ASZ);
        #pragma unroll
        for (int i = 0; i < 4; i++) {        // B: 64 k-rows x 16 x 16B
            int v = tid + (i << 8);
            int r = v >> 4, cq = v & 15;
            cp_async16(sB + (uint32_t)(r * PADN + (cq << 3)) * 2,
                       Bkn + (k0 + r) * ldb + (cq << 3));
        }
        cp_commit();
    };

    float acc[2][8][4] = {};

    const int npro = (nch < ST - 1) ? nch : ST - 1;
    for (int s = 0; s < npro; s++) load_chunk(s);

    for (int c = 0; c < nch; c++) {
        int pend = nch - 1 - c;
        if (pend > ST - 2) pend = ST - 2;
        cp_wait(pend);
        __syncthreads();
        int ln = c + ST - 1;
        if (ln < nch) load_chunk(ln);

        uint32_t sbase = smem_u32(smh + (c % ST) * STH);
        uint32_t aA = sbase + aOffH * 2;
        uint32_t bA = sbase + (ASZ + bOffH) * 2;
        #pragma unroll
        for (int ks = 0; ks < 4; ks++) {     // 4 x k16
            uint32_t a0[4], a1[4];
            ldsm4(a0, aA + ks * 32);
            ldsm4(a1, aA + ks * 32 + 16 * PADH * 2);
            #pragma unroll
            for (int g = 0; g < 4; g++) {    // 4 x n16
                uint32_t bb[4];
                ldsm4t(bb, bA + (ks * 16 * PADN + g * 16) * 2);
                mma_f16(acc[0][2 * g],     a0, bb[0], bb[1]);
                mma_f16(acc[0][2 * g + 1], a0, bb[2], bb[3]);
                mma_f16(acc[1][2 * g],     a1, bb[0], bb[1]);
                mma_f16(acc[1][2 * g + 1], a1, bb[2], bb[3]);
            }
        }
    }

    // ---------------- epilogue ----------------
    const int n0 = blockIdx.y * 128 + (wn << 6);
    const int m0 = blockIdx.x * 128 + (wm << 5);
    #pragma unroll
    for (int mt = 0; mt < 2; mt++) {
        #pragma unroll
        for (int half_ = 0; half_ < 2; half_++) {
            const int row = m0 + (mt << 4) + gid + (half_ << 3);
            const float* Rrow = resid ? (resid + (long long)row * ldc) : nullptr;
            #pragma unroll
            for (int nt = 0; nt < 8; nt++) {
                const int col = n0 + (nt << 3) + (tig << 1);
                float v0 = acc[mt][nt][(half_ << 1) + 0];
                float v1 = acc[mt][nt][(half_ << 1) + 1];
                if (epi != EPI_NONE) { v0 += bias[col]; v1 += bias[col + 1]; }
                if (epi == EPI_BIAS_RES) {
                    float2 rr = *(const float2*)(Rrow + col);
                    v0 += rr.x; v1 += rr.y;
                } else if (epi == EPI_BIAS_GELU) {
                    v0 = gelu_exact(v0); v1 = gelu_exact(v1);
                }
                if (Ch) {
                    *(__half2*)(Ch + (long long)row * ldc + col) =
                        __floats2half2_rn(v0, v1);
                } else {
                    *(float2*)(C + (long long)row * ldc + col) = make_float2(v0, v1);
                }
            }
        }
    }
}

// ---------------- launcher ----------------
extern "C" void kernel_launch(void* const* d_in, const int* in_sizes, int n_in,
                              void* d_out, int out_size)
{
    (void)in_sizes; (void)n_in; (void)out_size;
    const float* x    = (const float*)d_in[0];
    const float* ln1s = (const float*)d_in[1];
    const float* ln1b = (const float*)d_in[2];
    const float* ln2s = (const float*)d_in[3];
    const float* ln2b = (const float*)d_in[4];
    const float* Wq   = (const float*)d_in[5];
    const float* bq   = (const float*)d_in[6];
    const float* Wk   = (const float*)d_in[7];
    const float* bk   = (const float*)d_in[8];
    const float* Wv   = (const float*)d_in[9];
    const float* bv   = (const float*)d_in[10];
    const float* Wo   = (const float*)d_in[11];
    const float* bo   = (const float*)d_in[12];
    const float* W1   = (const float*)d_in[13];
    const float* b1   = (const float*)d_in[14];
    const float* W2   = (const float*)d_in[15];
    const float* b2   = (const float*)d_in[16];
    float* out = (float*)d_out;

    __half *y, *qkv, *o, *ffn, *Wqkv, *WoH, *W1H, *W2H;
    float  *x1, *bqkv;
    cudaGetSymbolAddress((void**)&y,    g_y);
    cudaGetSymbolAddress((void**)&qkv,  g_qkv);
    cudaGetSymbolAddress((void**)&o,    g_o);
    cudaGetSymbolAddress((void**)&ffn,  g_ffn);
    cudaGetSymbolAddress((void**)&Wqkv, g_Wqkv);
    cudaGetSymbolAddress((void**)&WoH,  g_WoH);
    cudaGetSymbolAddress((void**)&W1H,  g_W1H);
    cudaGetSymbolAddress((void**)&W2H,  g_W2H);
    cudaGetSymbolAddress((void**)&x1,   g_x1);
    cudaGetSymbolAddress((void**)&bqkv, g_bqkv);

    const int SMEMG  = 3 * (128 * 72 + 64 * 136) * 2;      // 107520
    const int SMEMFL = (4 * 64 * 72 + 128 * 72) * 2;       // 55296
    cudaFuncSetAttribute(gemm_h,       cudaFuncAttributeMaxDynamicSharedMemorySize, SMEMG);
    cudaFuncSetAttribute(flash_kernel, cudaFuncAttributeMaxDynamicSharedMemorySize, SMEMFL);

    // 0) LN1 -> y (half)
    ln_kernel<<<S_LEN, 256>>>(x, ln1s, ln1b, y);

    // 1) merged weight converts + bias concat
    prep_kernel<<<12289, 256>>>(Wq, Wk, Wv, Wo, W1, W2, bq, bk, bv,
                                Wqkv, WoH, W1H, W2H, bqkv);

    // 2) fused QKV projection -> qkv (half)
    gemm_h<<<dim3(S_LEN / 128, QKV_N / 128), 256, SMEMG>>>(
        y, D_DIM, Wqkv, QKV_N, nullptr, qkv, QKV_N, D_DIM, bqkv, nullptr, EPI_BIAS);

    // 3) RoPE on q and k (one warp per token, 32x sincos reuse)
    rope_kernel<<<S_LEN * 32 / 256, 256>>>(qkv);

    // 4) fused attention -> o (half); V read in-place from qkv
    flash_kernel<<<dim3(S_LEN / 128, NH), 256, SMEMFL>>>(
        qkv, qkv + 1024, qkv + 2048, QKV_N, o);

    // 5) x1 = o @ Wo + bo + x  (fp32 out)
    gemm_h<<<dim3(S_LEN / 128, D_DIM / 128), 256, SMEMG>>>(
        o, D_DIM, WoH, D_DIM, x1, nullptr, D_DIM, D_DIM, bo, x, EPI_BIAS_RES);

    // 6) LN2 -> y (half)
    ln_kernel<<<S_LEN, 256>>>(x1, ln2s, ln2b, y);

    // 7) ffn = gelu(y @ W1 + b1) (half out)
    gemm_h<<<dim3(S_LEN / 128, FF_D / 128), 256, SMEMG>>>(
        y, D_DIM, W1H, FF_D, nullptr, ffn, FF_D, D_DIM, b1, nullptr, EPI_BIAS_GELU);

    // 8) out = ffn @ W2 + b2 + x1 (fp32 out)
    gemm_h<<<dim3(S_LEN / 128, D_DIM / 128), 256, SMEMG>>>(
        ffn, FF_D, W2H, D_DIM, out, nullptr, D_DIM, FF_D, b2, x1, EPI_BIAS_RES);
}

// round 16
// speedup vs baseline: 1.2348x; 1.0227x over previous
#include <cuda_runtime.h>
#include <cuda_fp16.h>
#include <cstdint>
#include <math.h>

// Problem constants
#define S_LEN 4096
#define D_DIM 1024
#define NH    16
#define HDIM  64
#define KT    64
#define FF_D  4096
#define QKV_N 3072

#define EPI_NONE      0
#define EPI_BIAS      1
#define EPI_BIAS_RES  2
#define EPI_BIAS_GELU 3

// ---------------- scratch (device globals: allocation-free rule) ----------------
__device__ __half g_y   [S_LEN * D_DIM];
__device__ __half g_qkv [S_LEN * QKV_N];             // [S][3072]: q | k | v
__device__ __half g_o   [S_LEN * D_DIM];
__device__ __half g_ffn [(long long)S_LEN * FF_D];
__device__ __half g_Wqkv[(long long)D_DIM * QKV_N];  // [1024][3072] K-major
__device__ __half g_WoH [D_DIM * D_DIM];             // [1024][1024] K-major
__device__ __half g_W1H [(long long)D_DIM * FF_D];   // [1024][4096] K-major
__device__ __half g_W2H [(long long)FF_D * D_DIM];   // [4096][1024] K-major
__device__ float  g_x1  [S_LEN * D_DIM];
__device__ float  g_bqkv[QKV_N];

// ---------------- helpers ----------------
__device__ __forceinline__ uint32_t smem_u32(const void* p) {
    uint32_t a;
    asm("{ .reg .u64 t; cvta.to.shared.u64 t, %1; cvt.u32.u64 %0, t; }" : "=r"(a) : "l"(p));
    return a;
}
__device__ __forceinline__ void cp_async16(uint32_t s, const void* g) {
    asm volatile("cp.async.cg.shared.global [%0], [%1], 16;" :: "r"(s), "l"(g));
}
__device__ __forceinline__ void cp_commit() {
    asm volatile("cp.async.commit_group;" ::: "memory");
}
__device__ __forceinline__ void cp_wait(int n) {
    if (n == 0)      asm volatile("cp.async.wait_group 0;" ::: "memory");
    else if (n == 1) asm volatile("cp.async.wait_group 1;" ::: "memory");
    else             asm volatile("cp.async.wait_group 2;" ::: "memory");
}
__device__ __forceinline__ void ldsm4(uint32_t* r, uint32_t a) {
    asm volatile("ldmatrix.sync.aligned.m8n8.x4.shared.b16 {%0,%1,%2,%3}, [%4];"
        : "=r"(r[0]), "=r"(r[1]), "=r"(r[2]), "=r"(r[3]) : "r"(a));
}
__device__ __forceinline__ void ldsm4t(uint32_t* r, uint32_t a) {
    asm volatile("ldmatrix.sync.aligned.m8n8.x4.trans.shared.b16 {%0,%1,%2,%3}, [%4];"
        : "=r"(r[0]), "=r"(r[1]), "=r"(r[2]), "=r"(r[3]) : "r"(a));
}
__device__ __forceinline__ void mma_f16(float* c, const uint32_t* a,
                                        uint32_t b0, uint32_t b1) {
    asm volatile(
        "mma.sync.aligned.m16n8k16.row.col.f32.f16.f16.f32 "
        "{%0,%1,%2,%3}, {%4,%5,%6,%7}, {%8,%9}, {%0,%1,%2,%3};"
        : "+f"(c[0]), "+f"(c[1]), "+f"(c[2]), "+f"(c[3])
        : "r"(a[0]), "r"(a[1]), "r"(a[2]), "r"(a[3]), "r"(b0), "r"(b1));
}
__device__ __forceinline__ uint32_t h2exp2_(uint32_t x) {
    uint32_t r;
    asm("ex2.approx.f16x2 %0, %1;" : "=r"(r) : "r"(x));
    return r;
}
__device__ __forceinline__ float gelu_exact(float v) {
    return 0.5f * v * (1.0f + erff(v * 0.70710678118654752f));
}

// ---------------- LayerNorm (fp32 in, fp16 out) ----------------
__global__ __launch_bounds__(256) void ln_kernel(const float* __restrict__ x,
                                                 const float* __restrict__ sc,
                                                 const float* __restrict__ bi,
                                                 __half* __restrict__ y)
{
    long long row = blockIdx.x;
    const float* xr = x + row * D_DIM;
    int c = threadIdx.x << 2;
    float4 xv = *(const float4*)(xr + c);
    float s  = xv.x + xv.y + xv.z + xv.w;
    float ss = xv.x*xv.x + xv.y*xv.y + xv.z*xv.z + xv.w*xv.w;
    #pragma unroll
    for (int off = 16; off; off >>= 1) {
        s  += __shfl_down_sync(0xffffffffu, s,  off);
        ss += __shfl_down_sync(0xffffffffu, ss, off);
    }
    __shared__ float sbuf[8], ssbuf[8];
    __shared__ float mu_s, rinv_s;
    int w = threadIdx.x >> 5, l = threadIdx.x & 31;
    if (l == 0) { sbuf[w] = s; ssbuf[w] = ss; }
    __syncthreads();
    if (threadIdx.x == 0) {
        float S = 0.f, SS = 0.f;
        #pragma unroll
        for (int i = 0; i < 8; i++) { S += sbuf[i]; SS += ssbuf[i]; }
        float mu  = S * (1.0f / D_DIM);
        float var = SS * (1.0f / D_DIM) - mu * mu;
        mu_s = mu;
        rinv_s = rsqrtf(var + 1e-6f);
    }
    __syncthreads();
    float mu = mu_s, rinv = rinv_s;
    float4 scv = *(const float4*)(sc + c);
    float4 bv  = *(const float4*)(bi + c);
    __half2 h0 = __floats2half2_rn((xv.x - mu) * rinv * scv.x + bv.x,
                                   (xv.y - mu) * rinv * scv.y + bv.y);
    __half2 h1 = __floats2half2_rn((xv.z - mu) * rinv * scv.z + bv.z,
                                   (xv.w - mu) * rinv * scv.w + bv.w);
    uint2 pk;
    pk.x = *(uint32_t*)&h0; pk.y = *(uint32_t*)&h1;
    *(uint2*)(y + row * D_DIM + c) = pk;
}

// ---------------- RoPE: one warp per token, angles computed once, 16h x {q,k} ----
__global__ __launch_bounds__(256) void rope_kernel(__half* __restrict__ qkv)
{
    int idx = blockIdx.x * 256 + threadIdx.x;    // 4096*32 threads
    int s = idx >> 5, c = idx & 31;
    float freq = expf(-(float)c * (9.210340371976184f / 32.0f));
    float ang = (float)s * freq;
    float sn, cs;
    sincosf(ang, &sn, &cs);
    __half* base = qkv + (long long)s * QKV_N;
    #pragma unroll
    for (int h = 0; h < NH; h++) {
        __half* pq = base + h * HDIM;
        float q1 = __half2float(pq[c]), q2 = __half2float(pq[c + 32]);
        pq[c]      = __float2half_rn((q1 * cs - q2 * sn) * 0.125f);
        pq[c + 32] = __float2half_rn((q2 * cs + q1 * sn) * 0.125f);
        __half* pk = base + 1024 + h * HDIM;
        float k1 = __half2float(pk[c]), k2 = __half2float(pk[c + 32]);
        pk[c]      = __float2half_rn(k1 * cs - k2 * sn);
        pk[c + 32] = __float2half_rn(k2 * cs + k1 * sn);
    }
}

// ---------------- merged prep: 6 weight converts + bias concat, MLP=4 ----------------
// float4 index space (3145728 total):
//   [0, 786432)        Wq|Wk|Wv -> Wqkv column-interleaved
//   [786432, 1048576)  Wo  -> WoH  (flat)
//   [1048576, 2097152) W1  -> W1H  (flat)
//   [2097152, 3145728) W2  -> W2H  (flat)
// Each thread handles 4 consecutive float4 (independent loads). Block 3072: bias.
__global__ __launch_bounds__(256) void prep_kernel(
    const float* __restrict__ Wq, const float* __restrict__ Wk,
    const float* __restrict__ Wv, const float* __restrict__ Wo,
    const float* __restrict__ W1, const float* __restrict__ W2,
    const float* __restrict__ bq, const float* __restrict__ bk,
    const float* __restrict__ bv,
    __half* __restrict__ Wqkv, __half* __restrict__ WoH,
    __half* __restrict__ W1H,  __half* __restrict__ W2H,
    float* __restrict__ bqkv)
{
    if (blockIdx.x == 3072) {
        #pragma unroll
        for (int it = 0; it < 12; it++) {
            int i = it * 256 + threadIdx.x;
            bqkv[i] = (i < 1024) ? bq[i] : ((i < 2048) ? bk[i - 1024] : bv[i - 2048]);
        }
        return;
    }
    long long base = ((long long)blockIdx.x * 256 + threadIdx.x) * 4;
    float4 v[4];
    __half* dst[4];
    #pragma unroll
    for (int j = 0; j < 4; j++) {
        long long i4 = base + j;
        if (i4 < 786432) {                       // QKV interleave
            int seg = (int)(i4 >> 18);
            long long r = i4 & 262143;
            const float* in = (seg == 0) ? Wq : (seg == 1) ? Wk : Wv;
            long long k = r >> 8;                // 256 float4 per row
            int n = (int)(r & 255) << 2;
            v[j] = *(const float4*)(in + (k << 10) + n);
            dst[j] = Wqkv + k * QKV_N + (seg << 10) + n;
        } else if (i4 < 1048576) {               // Wo flat
            long long r = i4 - 786432;
            v[j] = *(const float4*)(Wo + (r << 2));
            dst[j] = WoH + (r << 2);
        } else if (i4 < 2097152) {               // W1 flat
            long long r = i4 - 1048576;
            v[j] = *(const float4*)(W1 + (r << 2));
            dst[j] = W1H + (r << 2);
        } else {                                 // W2 flat
            long long r = i4 - 2097152;
            v[j] = *(const float4*)(W2 + (r << 2));
            dst[j] = W2H + (r << 2);
        }
    }
    #pragma unroll
    for (int j = 0; j < 4; j++) {
        __half2 h0 = __floats2half2_rn(v[j].x, v[j].y);
        __half2 h1 = __floats2half2_rn(v[j].z, v[j].w);
        uint2 pk;
        pk.x = *(uint32_t*)&h0; pk.y = *(uint32_t*)&h1;
        *(uint2*)dst[j] = pk;
    }
}

// ---------------- fused flash attention (fp16 operands, fp32 accum) ----------------
// One CTA = (128 q-rows, one head). 8 warps, each owns 16 q-rows.
// K/V tiles of 64 keys, double-buffered cp.async. Online softmax with
// ex2.approx.f16x2; P kept in registers (C-fragment == A-fragment reuse).
__global__ __launch_bounds__(256, 2) void flash_kernel(
    const __half* __restrict__ q, const __half* __restrict__ k,
    const __half* __restrict__ v, int ldqk, __half* __restrict__ o)
{
    constexpr int PADH = 72;                 // halves per smem row (64 + 8)
    constexpr int TSZ  = 64 * PADH;          // halves
    constexpr float L2E = 1.4426950408889634f;
    extern __shared__ __half smh[];
    __half* Ks = smh;                        // [2][64][PADH] (also Q staging)
    __half* Vs = smh + 2 * TSZ;              // [2][64][PADH]

    const int tid  = threadIdx.x;
    const int wid  = tid >> 5, lane = tid & 31;
    const int gid  = lane >> 2, tig = lane & 3;
    const int h    = blockIdx.y;
    const int m0   = blockIdx.x * 128;

    // ldmatrix lane offsets (halves)
    const int aOffH = (wid * 16 + (lane & 15)) * PADH + ((lane >> 4) << 3);
    const int bOffH = (lane & 15) * PADH + ((lane >> 4) << 3);
    // trans offset for V ([j][d] tile -> B fragments of V^T)
    const int vOffH = ((lane & 7) + (((lane >> 3) & 1) << 3)) * PADH +
                      (((lane >> 4) & 1) << 3);

    // ---- stage Q tile (128 x 64 halves) in Ks region, extract fragments ----
    {
        uint32_t sQ = smem_u32(Ks);
        #pragma unroll
        for (int i = 0; i < 4; i++) {        // 128 rows x 8 x 16B
            int t = tid + (i << 8);
            int r = t >> 3, kq = t & 7;
            cp_async16(sQ + (uint32_t)(r * PADH + (kq << 3)) * 2,
                       q + (long long)(m0 + r) * ldqk + h * HDIM + (kq << 3));
        }
        cp_commit();
    }
    cp_wait(0);
    __syncthreads();

    uint32_t qf[4][4];
    {
        uint32_t qA = smem_u32(Ks) + aOffH * 2;
        #pragma unroll
        for (int ks = 0; ks < 4; ks++) ldsm4(qf[ks], qA + ks * 32);
    }
    __syncthreads();                         // Ks now reusable for K tiles

    float oacc[8][4] = {};
    float m0r = -1e30f, m1r = -1e30f;
    float l0r = 0.f,    l1r = 0.f;

    auto load_tile = [&](int kt) {
        int st = kt & 1;
        uint32_t sK = smem_u32(Ks + st * TSZ);
        uint32_t sV = smem_u32(Vs + st * TSZ);
        const long long j0 = (long long)kt * KT;
        #pragma unroll
        for (int i = 0; i < 2; i++) {        // K: 64 rows x 8 x 16B
            int t = tid + (i << 8);
            int r = t >> 3, kq = t & 7;
            cp_async16(sK + (uint32_t)(r * PADH + (kq << 3)) * 2,
                       k + (j0 + r) * ldqk + h * HDIM + (kq << 3));
        }
        #pragma unroll
        for (int i = 0; i < 2; i++) {        // V: same [keys][dims] layout
            int t = tid + (i << 8);
            int r = t >> 3, kq = t & 7;
            cp_async16(sV + (uint32_t)(r * PADH + (kq << 3)) * 2,
                       v + (j0 + r) * ldqk + h * HDIM + (kq << 3));
        }
        cp_commit();
    };

    load_tile(0);

    for (int kt = 0; kt < S_LEN / KT; kt++) {
        cp_wait(0);
        __syncthreads();
        if (kt + 1 < S_LEN / KT) load_tile(kt + 1);

        const __half* Kt = Ks + (kt & 1) * TSZ;
        const __half* Vt = Vs + (kt & 1) * TSZ;

        // ---- S = Q @ K^T (16 x 64 per warp) ----
        float sacc[8][4] = {};
        {
            uint32_t kA = smem_u32(Kt) + bOffH * 2;
            #pragma unroll
            for (int ks = 0; ks < 4; ks++) {
                #pragma unroll
                for (int g = 0; g < 4; g++) {
                    uint32_t bb[4];
                    ldsm4(bb, kA + ks * 32 + g * 16 * PADH * 2);
                    mma_f16(sacc[2 * g],     qf[ks], bb[0], bb[2]);
                    mma_f16(sacc[2 * g + 1], qf[ks], bb[1], bb[3]);
                }
            }
        }

        // ---- online softmax; P produced as packed fp16 A-fragments in regs ----
        float mx0 = -1e30f, mx1 = -1e30f;
        #pragma unroll
        for (int nt = 0; nt < 8; nt++) {
            mx0 = fmaxf(mx0, fmaxf(sacc[nt][0], sacc[nt][1]));
            mx1 = fmaxf(mx1, fmaxf(sacc[nt][2], sacc[nt][3]));
        }
        mx0 = fmaxf(mx0, __shfl_xor_sync(0xffffffffu, mx0, 1));
        mx0 = fmaxf(mx0, __shfl_xor_sync(0xffffffffu, mx0, 2));
        mx1 = fmaxf(mx1, __shfl_xor_sync(0xffffffffu, mx1, 1));
        mx1 = fmaxf(mx1, __shfl_xor_sync(0xffffffffu, mx1, 2));
        float mn0 = fmaxf(m0r, mx0), mn1 = fmaxf(m1r, mx1);
        float sc0 = __expf(m0r - mn0), sc1 = __expf(m1r - mn1);
        m0r = mn0; m1r = mn1;

        float mnl0 = mn0 * L2E, mnl1 = mn1 * L2E;
        float rs0 = 0.f, rs1 = 0.f;
        uint32_t pf[8][2];                   // pf[nt][0]: rows(gid), [1]: rows(gid+8)
        #pragma unroll
        for (int nt = 0; nt < 8; nt++) {
            __half2 t0 = __floats2half2_rn(fmaf(sacc[nt][0], L2E, -mnl0),
                                           fmaf(sacc[nt][1], L2E, -mnl0));
            __half2 t1 = __floats2half2_rn(fmaf(sacc[nt][2], L2E, -mnl1),
                                           fmaf(sacc[nt][3], L2E, -mnl1));
            pf[nt][0] = h2exp2_(*(uint32_t*)&t0);
            pf[nt][1] = h2exp2_(*(uint32_t*)&t1);
            float2 f0 = __half22float2(*(__half2*)&pf[nt][0]);
            float2 f1 = __half22float2(*(__half2*)&pf[nt][1]);
            rs0 += f0.x + f0.y;
            rs1 += f1.x + f1.y;
        }
        rs0 += __shfl_xor_sync(0xffffffffu, rs0, 1);
        rs0 += __shfl_xor_sync(0xffffffffu, rs0, 2);
        rs1 += __shfl_xor_sync(0xffffffffu, rs1, 1);
        rs1 += __shfl_xor_sync(0xffffffffu, rs1, 2);
        l0r = l0r * sc0 + rs0;
        l1r = l1r * sc1 + rs1;

        #pragma unroll
        for (int nt = 0; nt < 8; nt++) {
            oacc[nt][0] *= sc0; oacc[nt][1] *= sc0;
            oacc[nt][2] *= sc1; oacc[nt][3] *= sc1;
        }

        // ---- O += P @ V, A-fragments straight from pf ----
        {
            uint32_t vA = smem_u32(Vt) + vOffH * 2;
            #pragma unroll
            for (int ks = 0; ks < 4; ks++) {     // ks over key k16-chunks
                uint32_t a[4] = { pf[2 * ks][0], pf[2 * ks][1],
                                  pf[2 * ks + 1][0], pf[2 * ks + 1][1] };
                #pragma unroll
                for (int g = 0; g < 4; g++) {    // g over dim groups (MMA n)
                    uint32_t bb[4];
                    ldsm4t(bb, vA + (ks * 16 * PADH + g * 16) * 2);
                    mma_f16(oacc[2 * g],     a, bb[0], bb[1]);
                    mma_f16(oacc[2 * g + 1], a, bb[2], bb[3]);
                }
            }
        }
    }

    // ---- epilogue: normalize, write half ----
    float rl0 = 1.f / l0r, rl1 = 1.f / l1r;
    const int r0 = m0 + wid * 16 + gid;
    #pragma unroll
    for (int nt = 0; nt < 8; nt++) {
        int c = h * HDIM + (nt << 3) + (tig << 1);
        *(__half2*)&o[(long long)r0 * D_DIM + c] =
            __floats2half2_rn(oacc[nt][0] * rl0, oacc[nt][1] * rl0);
        *(__half2*)&o[(long long)(r0 + 8) * D_DIM + c] =
            __floats2half2_rn(oacc[nt][2] * rl1, oacc[nt][3] * rl1);
    }
}

// ---------------- fp16 mma.sync GEMM (R10 winner), B K-major via ldmatrix.trans ----
// C[128x128 tile] = A[M,K]h * B[K,N]h, fp32 accum. 8 warps (4m x 2n), warp 32x64.
__global__ __launch_bounds__(256, 2) void gemm_h(
    const __half* __restrict__ A, int lda,
    const __half* __restrict__ Bkn, int ldb,
    float* __restrict__ C, __half* __restrict__ Ch, int ldc,
    int K,
    const float* __restrict__ bias,
    const float* __restrict__ resid,
    int epi)
{
    constexpr int ST   = 3;
    constexpr int PADH = 72;                 // A row: 64 + 8 halves
    constexpr int PADN = 136;                // B row: 128 + 8 halves
    constexpr int ASZ  = 128 * PADH;         // halves
    constexpr int BSZ  = 64 * PADN;
    constexpr int STH  = ASZ + BSZ;

    extern __shared__ __half smh[];
    const int tid  = threadIdx.x;
    const int wid  = tid >> 5, lane = tid & 31;
    const int gid  = lane >> 2, tig = lane & 3;
    const int wm   = wid & 3,  wn  = wid >> 2;

    A   += (long long)(blockIdx.x * 128) * lda;
    Bkn += blockIdx.y * 128;

    const int nch = K >> 6;

    // ldmatrix lane offsets (halves)
    const int aOffH = ((wm << 5) + (lane & 15)) * PADH + ((lane >> 4) << 3);
    const int bOffH = ((lane & 7) + (((lane >> 3) & 1) << 3)) * PADN +
                      (wn << 6) + (((lane >> 4) & 1) << 3);

    auto load_chunk = [&](int c) {
        __half* s = smh + (c % ST) * STH;
        const long long k0 = (long long)c << 6;
        uint32_t sA = smem_u32(s);
        #pragma unroll
        for (int i = 0; i < 4; i++) {        // A: 128 rows x 8 x 16B
            int v = tid + (i << 8);
            int r = v >> 3, kq = v & 7;
            cp_async16(sA + (uint32_t)(r * PADH + (kq << 3)) * 2,
                       A + (long long)r * lda + k0 + (kq << 3));
        }
        uint32_t sB = smem_u32(s + ASZ);
        #pragma unroll
        for (int i = 0; i < 4; i++) {        // B: 64 k-rows x 16 x 16B
            int v = tid + (i << 8);
            int r = v >> 4, cq = v & 15;
            cp_async16(sB + (uint32_t)(r * PADN + (cq << 3)) * 2,
                       Bkn + (k0 + r) * ldb + (cq << 3));
        }
        cp_commit();
    };

    float acc[2][8][4] = {};

    const int npro = (nch < ST - 1) ? nch : ST - 1;
    for (int s = 0; s < npro; s++) load_chunk(s);

    for (int c = 0; c < nch; c++) {
        int pend = nch - 1 - c;
        if (pend > ST - 2) pend = ST - 2;
        cp_wait(pend);
        __syncthreads();
        int ln = c + ST - 1;
        if (ln < nch) load_chunk(ln);

        uint32_t sbase = smem_u32(smh + (c % ST) * STH);
        uint32_t aA = sbase + aOffH * 2;
        uint32_t bA = sbase + (ASZ + bOffH) * 2;
        #pragma unroll
        for (int ks = 0; ks < 4; ks++) {     // 4 x k16
            uint32_t a0[4], a1[4];
            ldsm4(a0, aA + ks * 32);
            ldsm4(a1, aA + ks * 32 + 16 * PADH * 2);
            #pragma unroll
            for (int g = 0; g < 4; g++) {    // 4 x n16
                uint32_t bb[4];
                ldsm4t(bb, bA + (ks * 16 * PADN + g * 16) * 2);
                mma_f16(acc[0][2 * g],     a0, bb[0], bb[1]);
                mma_f16(acc[0][2 * g + 1], a0, bb[2], bb[3]);
                mma_f16(acc[1][2 * g],     a1, bb[0], bb[1]);
                mma_f16(acc[1][2 * g + 1], a1, bb[2], bb[3]);
            }
        }
    }

    // ---------------- epilogue ----------------
    const int n0 = blockIdx.y * 128 + (wn << 6);
    const int m0 = blockIdx.x * 128 + (wm << 5);
    #pragma unroll
    for (int mt = 0; mt < 2; mt++) {
        #pragma unroll
        for (int half_ = 0; half_ < 2; half_++) {
            const int row = m0 + (mt << 4) + gid + (half_ << 3);
            const float* Rrow = resid ? (resid + (long long)row * ldc) : nullptr;
            #pragma unroll
            for (int nt = 0; nt < 8; nt++) {
                const int col = n0 + (nt << 3) + (tig << 1);
                float v0 = acc[mt][nt][(half_ << 1) + 0];
                float v1 = acc[mt][nt][(half_ << 1) + 1];
                if (epi != EPI_NONE) { v0 += bias[col]; v1 += bias[col + 1]; }
                if (epi == EPI_BIAS_RES) {
                    float2 rr = *(const float2*)(Rrow + col);
                    v0 += rr.x; v1 += rr.y;
                } else if (epi == EPI_BIAS_GELU) {
                    v0 = gelu_exact(v0); v1 = gelu_exact(v1);
                }
                if (Ch) {
                    *(__half2*)(Ch + (long long)row * ldc + col) =
                        __floats2half2_rn(v0, v1);
                } else {
                    *(float2*)(C + (long long)row * ldc + col) = make_float2(v0, v1);
                }
            }
        }
    }
}

// ---------------- launcher ----------------
extern "C" void kernel_launch(void* const* d_in, const int* in_sizes, int n_in,
                              void* d_out, int out_size)
{
    (void)in_sizes; (void)n_in; (void)out_size;
    const float* x    = (const float*)d_in[0];
    const float* ln1s = (const float*)d_in[1];
    const float* ln1b = (const float*)d_in[2];
    const float* ln2s = (const float*)d_in[3];
    const float* ln2b = (const float*)d_in[4];
    const float* Wq   = (const float*)d_in[5];
    const float* bq   = (const float*)d_in[6];
    const float* Wk   = (const float*)d_in[7];
    const float* bk   = (const float*)d_in[8];
    const float* Wv   = (const float*)d_in[9];
    const float* bv   = (const float*)d_in[10];
    const float* Wo   = (const float*)d_in[11];
    const float* bo   = (const float*)d_in[12];
    const float* W1   = (const float*)d_in[13];
    const float* b1   = (const float*)d_in[14];
    const float* W2   = (const float*)d_in[15];
    const float* b2   = (const float*)d_in[16];
    float* out = (float*)d_out;

    __half *y, *qkv, *o, *ffn, *Wqkv, *WoH, *W1H, *W2H;
    float  *x1, *bqkv;
    cudaGetSymbolAddress((void**)&y,    g_y);
    cudaGetSymbolAddress((void**)&qkv,  g_qkv);
    cudaGetSymbolAddress((void**)&o,    g_o);
    cudaGetSymbolAddress((void**)&ffn,  g_ffn);
    cudaGetSymbolAddress((void**)&Wqkv, g_Wqkv);
    cudaGetSymbolAddress((void**)&WoH,  g_WoH);
    cudaGetSymbolAddress((void**)&W1H,  g_W1H);
    cudaGetSymbolAddress((void**)&W2H,  g_W2H);
    cudaGetSymbolAddress((void**)&x1,   g_x1);
    cudaGetSymbolAddress((void**)&bqkv, g_bqkv);

    const int SMEMG  = 3 * (128 * 72 + 64 * 136) * 2;      // 107520
    const int SMEMFL = 4 * 64 * 72 * 2;                    // 36864
    cudaFuncSetAttribute(gemm_h,       cudaFuncAttributeMaxDynamicSharedMemorySize, SMEMG);
    cudaFuncSetAttribute(flash_kernel, cudaFuncAttributeMaxDynamicSharedMemorySize, SMEMFL);

    // 0) LN1 -> y (half)
    ln_kernel<<<S_LEN, 256>>>(x, ln1s, ln1b, y);

    // 1) merged weight converts + bias concat (MLP=4)
    prep_kernel<<<3073, 256>>>(Wq, Wk, Wv, Wo, W1, W2, bq, bk, bv,
                               Wqkv, WoH, W1H, W2H, bqkv);

    // 2) fused QKV projection -> qkv (half)
    gemm_h<<<dim3(S_LEN / 128, QKV_N / 128), 256, SMEMG>>>(
        y, D_DIM, Wqkv, QKV_N, nullptr, qkv, QKV_N, D_DIM, bqkv, nullptr, EPI_BIAS);

    // 3) RoPE on q and k (one warp per token, 32x sincos reuse)
    rope_kernel<<<S_LEN * 32 / 256, 256>>>(qkv);

    // 4) fused attention -> o (half); V read in-place from qkv
    flash_kernel<<<dim3(S_LEN / 128, NH), 256, SMEMFL>>>(
        qkv, qkv + 1024, qkv + 2048, QKV_N, o);

    // 5) x1 = o @ Wo + bo + x  (fp32 out)
    gemm_h<<<dim3(S_LEN / 128, D_DIM / 128), 256, SMEMG>>>(
        o, D_DIM, WoH, D_DIM, x1, nullptr, D_DIM, D_DIM, bo, x, EPI_BIAS_RES);

    // 6) LN2 -> y (half)
    ln_kernel<<<S_LEN, 256>>>(x1, ln2s, ln2b, y);

    // 7) ffn = gelu(y @ W1 + b1) (half out)
    gemm_h<<<dim3(S_LEN / 128, FF_D / 128), 256, SMEMG>>>(
        y, D_DIM, W1H, FF_D, nullptr, ffn, FF_D, D_DIM, b1, nullptr, EPI_BIAS_GELU);

    // 8) out = ffn @ W2 + b2 + x1 (fp32 out)
    gemm_h<<<dim3(S_LEN / 128, D_DIM / 128), 256, SMEMG>>>(
        ffn, FF_D, W2H, D_DIM, out, nullptr, D_DIM, FF_D, b2, x1, EPI_BIAS_RES);
}